// round 10
// baseline (speedup 1.0000x reference)
#include <cuda_runtime.h>
#include <cuda_bf16.h>
#include <cstdint>

#define N_B 64
#define HW_ 1024
#define D_  512
#define K_  64
#define EPSF 1e-12f
#define RB   144     // A/B row bytes (72 bf16): ldmatrix conflict-free
#define RB2  272     // vlad B row bytes (136 bf16)

// ---------------- device scratch (allocation-free rule) ---------------------
__device__ unsigned short g_WTh[K_ * D_];                 // W^T hi bf16 [k][d]
__device__ unsigned short g_WTl[K_ * D_];                 // W^T lo bf16
__device__ unsigned short g_aTh[(size_t)N_B * K_ * HW_];  // a^T hi [n][k][hw]
__device__ unsigned short g_aTl[(size_t)N_B * K_ * HW_];  // a^T lo
__device__ float g_asum[N_B * K_];
__device__ float g_colsq[N_B * K_];

// ---------------- helpers ----------------------------------------------------
__device__ __forceinline__ uint32_t smem_u32(const void* p) {
    uint32_t a;
    asm("{ .reg .u64 t; cvta.to.shared.u64 t, %1; cvt.u32.u64 %0, t; }"
        : "=r"(a) : "l"(p));
    return a;
}
__device__ __forceinline__ void ldm4(uint32_t* r, uint32_t a) {
    asm volatile("ldmatrix.sync.aligned.m8n8.x4.shared.b16 {%0,%1,%2,%3}, [%4];"
                 : "=r"(r[0]), "=r"(r[1]), "=r"(r[2]), "=r"(r[3]) : "r"(a));
}
__device__ __forceinline__ void ldm4t(uint32_t* r, uint32_t a) {
    asm volatile("ldmatrix.sync.aligned.m8n8.x4.trans.shared.b16 {%0,%1,%2,%3}, [%4];"
                 : "=r"(r[0]), "=r"(r[1]), "=r"(r[2]), "=r"(r[3]) : "r"(a));
}
__device__ __forceinline__ void mma16816(float* d, const uint32_t* a,
                                         const uint32_t* b) {
    asm volatile(
        "mma.sync.aligned.m16n8k16.row.col.f32.bf16.bf16.f32 "
        "{%0,%1,%2,%3}, {%4,%5,%6,%7}, {%8,%9}, {%0,%1,%2,%3};"
        : "+f"(d[0]), "+f"(d[1]), "+f"(d[2]), "+f"(d[3])
        : "r"(a[0]), "r"(a[1]), "r"(a[2]), "r"(a[3]), "r"(b[0]), "r"(b[1]));
}
__device__ __forceinline__ void split2(float x0, float x1, uint32_t& hp, uint32_t& lp) {
    uint32_t u0 = __float_as_uint(x0), u1 = __float_as_uint(x1);
    hp = __byte_perm(u0, u1, 0x7632);
    float l0 = x0 - __uint_as_float(u0 & 0xFFFF0000u);
    float l1 = x1 - __uint_as_float(u1 & 0xFFFF0000u);
    asm("cvt.rn.bf16x2.f32 %0, %1, %2;" : "=r"(lp) : "f"(l1), "f"(l0));
}
__device__ __forceinline__ float fexp(float x) {
    x = fmaxf(x, -80.0f);
    float t = x * 1.4426950408889634f;
    float tb = t + 12582912.0f;
    float f = t - (tb - 12582912.0f);
    int ei = __float_as_int(tb) - 0x4B400000;
    float p = 1.5403530e-4f;
    p = fmaf(p, f, 1.3333558e-3f);
    p = fmaf(p, f, 9.6181291e-3f);
    p = fmaf(p, f, 5.5504109e-2f);
    p = fmaf(p, f, 2.4022651e-1f);
    p = fmaf(p, f, 6.9314718e-1f);
    p = fmaf(p, f, 1.0f);
    return p * __int_as_float((ei + 127) << 23);
}

// ---------------- K0 + prep --------------------------------------------------
__global__ void zero_kernel() {
    int t = blockIdx.x * blockDim.x + threadIdx.x;
    if (t < N_B * K_) { g_asum[t] = 0.f; g_colsq[t] = 0.f; }
}
__global__ void prep_kernel(const float* __restrict__ W) {
    int t = blockIdx.x * blockDim.x + threadIdx.x;
    if (t < D_ * K_) {
        int d = t >> 6, k = t & 63;
        float w = W[t];
        uint32_t u = __float_as_uint(w);
        g_WTh[k * D_ + d] = (unsigned short)(u >> 16);
        float lo = w - __uint_as_float(u & 0xFFFF0000u);
        __nv_bfloat16 lb = __float2bfloat16(lo);
        g_WTl[k * D_ + d] = *reinterpret_cast<unsigned short*>(&lb);
    }
}

// ================= GEMM1: assignment + softmax ===============================
// double-buffered stage: AH@0(18432) AL@18432 BH@36864(9216) BL@46080 -> 55296
#define AH1 0
#define AL1 18432
#define BH1 36864
#define BL1 46080
#define STG1 55296
#define BIAS1 110592
#define SMEM1 110848

#define ASG_MMA(base)                                                          \
    do {                                                                       \
        _Pragma("unroll")                                                      \
        for (int ks = 0; ks < 4; ks++) {                                       \
            uint32_t ah[2][4], al[2][4], bh[2][4], bl[2][4];                   \
            _Pragma("unroll")                                                  \
            for (int mt = 0; mt < 2; mt++) {                                   \
                uint32_t ad = sb + (base) + AH1 +                              \
                              (wm * 32 + mt * 16 + (lane & 15)) * RB +         \
                              (ks * 16 + (lane >> 4) * 8) * 2;                 \
                ldm4(ah[mt], ad);                                              \
                ldm4(al[mt], ad + (AL1 - AH1));                                \
            }                                                                  \
            _Pragma("unroll")                                                  \
            for (int np = 0; np < 2; np++) {                                   \
                uint32_t bd = sb + (base) + BH1 +                              \
                    (wn * 32 + np * 16 + (lane & 7) + ((lane >> 4) << 3)) * RB \
                    + (ks * 16 + ((lane >> 3) & 1) * 8) * 2;                   \
                ldm4(bh[np], bd);                                              \
                ldm4(bl[np], bd + (BL1 - BH1));                                \
            }                                                                  \
            _Pragma("unroll")                                                  \
            for (int mt = 0; mt < 2; mt++)                                     \
                _Pragma("unroll")                                              \
                for (int nt = 0; nt < 4; nt++) {                               \
                    const uint32_t* bph = &bh[nt >> 1][(nt & 1) * 2];          \
                    const uint32_t* bpl = &bl[nt >> 1][(nt & 1) * 2];          \
                    mma16816(acc[mt][nt], ah[mt], bph);                        \
                    mma16816(acc[mt][nt], ah[mt], bpl);                        \
                    mma16816(acc[mt][nt], al[mt], bph);                        \
                }                                                              \
        }                                                                      \
    } while (0)

// STS of register-held chunk into stage buffer `base`
#define ASG_STS(base)                                                          \
    do {                                                                       \
        _Pragma("unroll")                                                      \
        for (int j = 0; j < 8; j++) {                                          \
            uint32_t h01, l01, h23, l23;                                       \
            split2(ra[j].x, ra[j].y, h01, l01);                                \
            split2(ra[j].z, ra[j].w, h23, l23);                                \
            uint32_t off = (base) + arow * RB + (aseg + 8 * j) * 2;            \
            *(uint2*)(sm + AH1 + off) = make_uint2(h01, h23);                  \
            *(uint2*)(sm + AL1 + off) = make_uint2(l01, l23);                  \
        }                                                                      \
        {                                                                      \
            uint32_t boff = (base) + brow * RB + bseg * 2;                     \
            *(uint4*)(sm + BH1 + boff) = rbh[0];                               \
            *(uint4*)(sm + BH1 + boff + 16) = rbh[1];                          \
            *(uint4*)(sm + BL1 + boff) = rbl[0];                               \
            *(uint4*)(sm + BL1 + boff + 16) = rbl[1];                          \
        }                                                                      \
    } while (0)

#define ASG_LDG(c)                                                             \
    do {                                                                       \
        const float* xp = x + (size_t)(row0 + arow) * D_ + (c) * 64 + aseg;    \
        _Pragma("unroll")                                                      \
        for (int j = 0; j < 8; j++) ra[j] = *(const float4*)(xp + 8 * j);      \
        const unsigned short* wh = g_WTh + brow * D_ + (c) * 64 + bseg;        \
        const unsigned short* wl = g_WTl + brow * D_ + (c) * 64 + bseg;        \
        rbh[0] = *(const uint4*)wh; rbh[1] = *(const uint4*)(wh + 8);          \
        rbl[0] = *(const uint4*)wl; rbl[1] = *(const uint4*)(wl + 8);          \
    } while (0)

__global__ void __launch_bounds__(256, 2)
asg_kernel(const float* __restrict__ x, const float* __restrict__ bc) {
    extern __shared__ char sm[];
    const int tid = threadIdx.x, lane = tid & 31, wid = tid >> 5;
    const int wm = wid & 3, wn = wid >> 2;
    const int row0 = blockIdx.x * 128, n = blockIdx.x >> 3;
    const int hw0 = row0 & (HW_ - 1);
    const uint32_t sb = smem_u32(sm);

    if (tid < 64) ((float*)(sm + BIAS1))[tid] = bc[tid];

    float acc[2][4][4];
#pragma unroll
    for (int a = 0; a < 2; a++)
#pragma unroll
        for (int b = 0; b < 4; b++)
#pragma unroll
            for (int c = 0; c < 4; c++) acc[a][b][c] = 0.f;

    float4 ra[8];
    uint4 rbh[2], rbl[2];
    const int arow = tid >> 1, aseg = (tid & 1) * 4;
    const int brow = tid >> 2, bseg = (tid & 3) * 16;

    // prologue: stage chunk 0, prefetch chunk 1
    ASG_LDG(0);
    ASG_STS(0);
    ASG_LDG(1);
    __syncthreads();

    // pipeline: MMA(ch) || STS(ch+1) || LDG(ch+2); one sync per chunk
    for (int ch = 0; ch < 8; ch++) {
        int cur = (ch & 1) * STG1;
        int nxt = STG1 - cur;
        if (ch < 7) ASG_STS(nxt);
        if (ch < 6) ASG_LDG(ch + 2);
        ASG_MMA(cur);
        __syncthreads();
    }

    // scores -> SMEM s[128][66]
    float* s = (float*)sm;
#pragma unroll
    for (int mt = 0; mt < 2; mt++)
#pragma unroll
        for (int nt = 0; nt < 4; nt++) {
            int r = wm * 32 + mt * 16 + (lane >> 2);
            int col = wn * 32 + nt * 8 + 2 * (lane & 3);
            *(float2*)&s[r * 66 + col] = make_float2(acc[mt][nt][0], acc[mt][nt][1]);
            *(float2*)&s[(r + 8) * 66 + col] = make_float2(acc[mt][nt][2], acc[mt][nt][3]);
        }
    __syncthreads();

    if (tid < 128) {
        const float* bias = (const float*)(sm + BIAS1);
        float f[64];
        float m = -1e30f;
#pragma unroll
        for (int k = 0; k < 64; k++) { f[k] = s[tid * 66 + k] + bias[k]; m = fmaxf(m, f[k]); }
        float ssum = 0.f;
#pragma unroll
        for (int k = 0; k < 64; k++) { f[k] = fexp(f[k] - m); ssum += f[k]; }
        float inv = 1.0f / ssum;
#pragma unroll
        for (int k = 0; k < 64; k++) s[tid * 66 + k] = f[k] * inv;
    }
    __syncthreads();

    // coalesced a^T write: warp w -> k rows w*8..w*8+7, 128B runs per row
    {
        size_t nb = (size_t)n * K_ * HW_;
#pragma unroll
        for (int kk = 0; kk < 8; kk++) {
            int k = wid * 8 + kk;
#pragma unroll
            for (int half = 0; half < 2; half++) {
                int hw = half * 64 + 2 * lane;
                float a0 = s[hw * 66 + k];
                float a1 = s[(hw + 1) * 66 + k];
                uint32_t hp, lp;
                split2(a0, a1, hp, lp);
                size_t e = nb + (size_t)k * HW_ + hw0 + hw;
                *(uint32_t*)(g_aTh + e) = hp;
                *(uint32_t*)(g_aTl + e) = lp;
            }
        }
    }
    if (tid < 64) {
        float acc_s = 0.f;
#pragma unroll 8
        for (int r = 0; r < 128; r++) acc_s += s[r * 66 + tid];
        atomicAdd(&g_asum[n * K_ + tid], acc_s);
    }
}

// ================= GEMM2: V^T = a^T (64xHW) * x (HWx128d) ====================
// double-buffered stage: AH@0(9216) AL@9216 BH@18432(17408) BL@35840 -> 53248
#define AH2 0
#define AL2 9216
#define BH2 18432
#define BL2 35840
#define STG2 53248
#define AS2 106496
#define SMEM2 106752
#define VST 68       // v2 row stride in floats (272B, 16B-aligned)

#define VLAD_STS(base)                                                         \
    do {                                                                       \
        uint32_t aoff = (base) + crow * RB + cseg * 2;                         \
        *(uint4*)(sm + AH2 + aoff) = rah[0];                                   \
        *(uint4*)(sm + AH2 + aoff + 16) = rah[1];                              \
        *(uint4*)(sm + AL2 + aoff) = ral[0];                                   \
        *(uint4*)(sm + AL2 + aoff + 16) = ral[1];                              \
        _Pragma("unroll")                                                      \
        for (int j = 0; j < 8; j++) {                                          \
            uint32_t h01, l01, h23, l23;                                       \
            split2(rb[j].x, rb[j].y, h01, l01);                                \
            split2(rb[j].z, rb[j].w, h23, l23);                                \
            uint32_t off = (base) + xrow * RB2 + (xseg + 16 * j) * 2;          \
            *(uint2*)(sm + BH2 + off) = make_uint2(h01, h23);                  \
            *(uint2*)(sm + BL2 + off) = make_uint2(l01, l23);                  \
        }                                                                      \
    } while (0)

#define VLAD_LDG(c)                                                            \
    do {                                                                       \
        int hw1 = (c) * 64;                                                    \
        const unsigned short* ahp = ath + (size_t)crow * HW_ + hw1 + cseg;     \
        const unsigned short* alp = atl + (size_t)crow * HW_ + hw1 + cseg;     \
        rah[0] = *(const uint4*)ahp; rah[1] = *(const uint4*)(ahp + 8);        \
        ral[0] = *(const uint4*)alp; ral[1] = *(const uint4*)(alp + 8);        \
        const float* xp = xn + (size_t)(hw1 + xrow) * D_ + m0 + xseg;          \
        _Pragma("unroll")                                                      \
        for (int j = 0; j < 8; j++) rb[j] = *(const float4*)(xp + 16 * j);     \
    } while (0)

__global__ void __launch_bounds__(256, 2)
vlad_kernel(const float* __restrict__ x, const float* __restrict__ Cc,
            float* __restrict__ out) {
    extern __shared__ char sm[];
    const int tid = threadIdx.x, lane = tid & 31, wid = tid >> 5;
    const int wm = wid & 1, wn = wid >> 1;
    const int n = blockIdx.y, m0 = blockIdx.x * 128;
    const uint32_t sb = smem_u32(sm);

    if (tid < 64) ((float*)(sm + AS2))[tid] = g_asum[n * K_ + tid];

    const float* xn = x + (size_t)n * HW_ * D_;
    const unsigned short* ath = g_aTh + (size_t)n * K_ * HW_;
    const unsigned short* atl = g_aTl + (size_t)n * K_ * HW_;

    float acc[2][4][4];
#pragma unroll
    for (int a = 0; a < 2; a++)
#pragma unroll
        for (int b = 0; b < 4; b++)
#pragma unroll
            for (int c = 0; c < 4; c++) acc[a][b][c] = 0.f;

    uint4 rah[2], ral[2];
    float4 rb[8];
    const int crow = tid >> 2, cseg = (tid & 3) * 16;
    const int xrow = tid >> 2, xseg = (tid & 3) * 4;

    // prologue
    VLAD_LDG(0);
    VLAD_STS(0);
    VLAD_LDG(1);
    __syncthreads();

    for (int ch = 0; ch < 16; ch++) {
        int cur = (ch & 1) * STG2;
        int nxt = STG2 - cur;
        if (ch < 15) VLAD_STS(nxt);
        if (ch < 14) VLAD_LDG(ch + 2);
        // MMA on current buffer
#pragma unroll
        for (int ks = 0; ks < 4; ks++) {
            uint32_t ah[2][4], al[2][4], bh[2][4], bl[2][4];
#pragma unroll
            for (int mt = 0; mt < 2; mt++) {
                uint32_t ad = sb + cur + AH2 + (wm * 32 + mt * 16 + (lane & 15)) * RB
                              + (ks * 16 + (lane >> 4) * 8) * 2;
                ldm4(ah[mt], ad);
                ldm4(al[mt], ad + (AL2 - AH2));
            }
#pragma unroll
            for (int np = 0; np < 2; np++) {
                uint32_t bd = sb + cur + BH2 + (ks * 16 + (lane & 15)) * RB2
                              + (wn * 32 + np * 16 + (lane >> 4) * 8) * 2;
                ldm4t(bh[np], bd);
                ldm4t(bl[np], bd + (BL2 - BH2));
            }
#pragma unroll
            for (int mt = 0; mt < 2; mt++)
#pragma unroll
                for (int nt = 0; nt < 4; nt++) {
                    const uint32_t* bph = &bh[nt >> 1][(nt & 1) * 2];
                    const uint32_t* bpl = &bl[nt >> 1][(nt & 1) * 2];
                    mma16816(acc[mt][nt], ah[mt], bph);
                    mma16816(acc[mt][nt], ah[mt], bpl);
                    mma16816(acc[mt][nt], al[mt], bph);
                }
        }
        __syncthreads();
    }

    // epilogue: acc (c,d) -> smem v2[d][VST] transposed
    float* v2 = (float*)sm;   // 128 x 68 f32 = 34816 B (aliases buffer 0)
#pragma unroll
    for (int mt = 0; mt < 2; mt++)
#pragma unroll
        for (int nt = 0; nt < 4; nt++) {
            int c = wm * 32 + mt * 16 + (lane >> 2);
            int d = wn * 32 + nt * 8 + 2 * (lane & 3);
            v2[d * VST + c] = acc[mt][nt][0];
            v2[(d + 1) * VST + c] = acc[mt][nt][1];
            v2[d * VST + c + 8] = acc[mt][nt][2];
            v2[(d + 1) * VST + c + 8] = acc[mt][nt][3];
        }
    __syncthreads();

    // output: +asum*C, coalesced store, o^2 back to v2 for colsq
    {
        const float* asums = (const float*)(sm + AS2);
        int d = tid >> 1, kh = (tid & 1) * 32;
        int dg = m0 + d;
        float* po = out + ((size_t)n * D_ + dg) * K_ + kh;
        const float* pc = Cc + (size_t)dg * K_ + kh;
#pragma unroll
        for (int j = 0; j < 8; j++) {
            float4 v = *(float4*)&v2[d * VST + kh + 4 * j];
            float4 cc = *(const float4*)(pc + 4 * j);
            float4 as = *(const float4*)(asums + kh + 4 * j);
            float4 o;
            o.x = fmaf(as.x, cc.x, v.x);
            o.y = fmaf(as.y, cc.y, v.y);
            o.z = fmaf(as.z, cc.z, v.z);
            o.w = fmaf(as.w, cc.w, v.w);
            *(float4*)(po + 4 * j) = o;
            float4 sq = make_float4(o.x * o.x, o.y * o.y, o.z * o.z, o.w * o.w);
            *(float4*)&v2[d * VST + kh + 4 * j] = sq;
        }
    }
    __syncthreads();
    if (tid < 64) {
        float s = 0.f;
#pragma unroll 8
        for (int d2 = 0; d2 < 128; d2++) s += v2[d2 * VST + tid];
        atomicAdd(&g_colsq[n * K_ + tid], s);
    }
}

// ---------------- norm -------------------------------------------------------
__global__ void norm2_kernel(float* __restrict__ out) {
    __shared__ float S[64];
    __shared__ float sc[64];
    __shared__ float gsh;
    const int n = blockIdx.y, tid = threadIdx.x;
    if (tid < 64) S[tid] = g_colsq[n * K_ + tid];
    __syncthreads();
    if (tid == 0) {
        float s = 0.f;
#pragma unroll
        for (int k = 0; k < 64; k++) s += S[k] / (S[k] + EPSF);
        gsh = rsqrtf(s + EPSF);
    }
    __syncthreads();
    if (tid < 64) sc[tid] = rsqrtf(S[tid] + EPSF) * gsh;
    __syncthreads();
    float* po = out + (size_t)n * D_ * K_ + blockIdx.x * 4096;
#pragma unroll
    for (int i = 0; i < 4; i++) {
        int e = tid * 4 + i * 1024;
        float4 v = *(float4*)(po + e);
        int k = e & 63;
        v.x *= sc[k + 0]; v.y *= sc[k + 1];
        v.z *= sc[k + 2]; v.w *= sc[k + 3];
        *(float4*)(po + e) = v;
    }
}

// ---------------------------------------------------------------------------
extern "C" void kernel_launch(void* const* d_in, const int* in_sizes, int n_in,
                              void* d_out, int out_size) {
    const float* x = (const float*)d_in[0];   // [64,32,32,512]
    const float* W = (const float*)d_in[1];   // [512,64]
    const float* b = (const float*)d_in[2];   // [64]
    const float* C = (const float*)d_in[3];   // [512,64]
    float* out = (float*)d_out;               // [64, 32768]

    cudaFuncSetAttribute(asg_kernel, cudaFuncAttributeMaxDynamicSharedMemorySize, SMEM1);
    cudaFuncSetAttribute(vlad_kernel, cudaFuncAttributeMaxDynamicSharedMemorySize, SMEM2);

    zero_kernel<<<16, 256>>>();
    prep_kernel<<<128, 256>>>(W);
    asg_kernel<<<512, 256, SMEM1>>>(x, b);
    vlad_kernel<<<dim3(4, 64), 256, SMEM2>>>(x, C, out);
    norm2_kernel<<<dim3(8, 64), 256>>>(out);
}

// round 11
// speedup vs baseline: 1.1680x; 1.1680x over previous
#include <cuda_runtime.h>
#include <cuda_bf16.h>
#include <cstdint>

#define N_B 64
#define HW_ 1024
#define D_  512
#define K_  64
#define EPSF 1e-12f
#define RB   144     // A/B row bytes (72 bf16): ldmatrix conflict-free
#define RB2  272     // vlad B row bytes (136 bf16)

// ---------------- device scratch (allocation-free rule) ---------------------
__device__ unsigned short g_WTh[K_ * D_];                 // W^T hi bf16 [k][d]
__device__ unsigned short g_WTl[K_ * D_];                 // W^T lo bf16
__device__ unsigned short g_aTh[(size_t)N_B * K_ * HW_];  // a^T hi [n][k][hw]
__device__ unsigned short g_aTl[(size_t)N_B * K_ * HW_];  // a^T lo
__device__ float g_asum[N_B * K_];
__device__ float g_colsq[N_B * K_];

// ---------------- helpers ----------------------------------------------------
__device__ __forceinline__ uint32_t smem_u32(const void* p) {
    uint32_t a;
    asm("{ .reg .u64 t; cvta.to.shared.u64 t, %1; cvt.u32.u64 %0, t; }"
        : "=r"(a) : "l"(p));
    return a;
}
__device__ __forceinline__ void ldm4(uint32_t* r, uint32_t a) {
    asm volatile("ldmatrix.sync.aligned.m8n8.x4.shared.b16 {%0,%1,%2,%3}, [%4];"
                 : "=r"(r[0]), "=r"(r[1]), "=r"(r[2]), "=r"(r[3]) : "r"(a));
}
__device__ __forceinline__ void ldm4t(uint32_t* r, uint32_t a) {
    asm volatile("ldmatrix.sync.aligned.m8n8.x4.trans.shared.b16 {%0,%1,%2,%3}, [%4];"
                 : "=r"(r[0]), "=r"(r[1]), "=r"(r[2]), "=r"(r[3]) : "r"(a));
}
__device__ __forceinline__ void mma16816(float* d, const uint32_t* a,
                                         const uint32_t* b) {
    asm volatile(
        "mma.sync.aligned.m16n8k16.row.col.f32.bf16.bf16.f32 "
        "{%0,%1,%2,%3}, {%4,%5,%6,%7}, {%8,%9}, {%0,%1,%2,%3};"
        : "+f"(d[0]), "+f"(d[1]), "+f"(d[2]), "+f"(d[3])
        : "r"(a[0]), "r"(a[1]), "r"(a[2]), "r"(a[3]), "r"(b[0]), "r"(b[1]));
}
__device__ __forceinline__ void split2(float x0, float x1, uint32_t& hp, uint32_t& lp) {
    uint32_t u0 = __float_as_uint(x0), u1 = __float_as_uint(x1);
    hp = __byte_perm(u0, u1, 0x7632);
    float l0 = x0 - __uint_as_float(u0 & 0xFFFF0000u);
    float l1 = x1 - __uint_as_float(u1 & 0xFFFF0000u);
    asm("cvt.rn.bf16x2.f32 %0, %1, %2;" : "=r"(lp) : "f"(l1), "f"(l0));
}
__device__ __forceinline__ float fexp(float x) {
    x = fmaxf(x, -80.0f);
    float t = x * 1.4426950408889634f;
    float tb = t + 12582912.0f;
    float f = t - (tb - 12582912.0f);
    int ei = __float_as_int(tb) - 0x4B400000;
    float p = 1.5403530e-4f;
    p = fmaf(p, f, 1.3333558e-3f);
    p = fmaf(p, f, 9.6181291e-3f);
    p = fmaf(p, f, 5.5504109e-2f);
    p = fmaf(p, f, 2.4022651e-1f);
    p = fmaf(p, f, 6.9314718e-1f);
    p = fmaf(p, f, 1.0f);
    return p * __int_as_float((ei + 127) << 23);
}

// ---------------- prep: W split + accumulator zeroing (merged) ---------------
__global__ void prep_kernel(const float* __restrict__ W) {
    int t = blockIdx.x * blockDim.x + threadIdx.x;
    if (t < N_B * K_) { g_asum[t] = 0.f; g_colsq[t] = 0.f; }
    if (t < D_ * K_) {
        int d = t >> 6, k = t & 63;
        float w = W[t];
        uint32_t u = __float_as_uint(w);
        g_WTh[k * D_ + d] = (unsigned short)(u >> 16);
        float lo = w - __uint_as_float(u & 0xFFFF0000u);
        __nv_bfloat16 lb = __float2bfloat16(lo);
        g_WTl[k * D_ + d] = *reinterpret_cast<unsigned short*>(&lb);
    }
}

// ================= GEMM1: assignment + softmax ===============================
// single-buffer, occ 3: no register prefetch; 6 warps/SMSP cover LDG latency
#define AH1 0
#define AL1 18432
#define BH1 36864
#define BL1 46080
#define BIAS1 55296
#define SMEM1 55552

__global__ void __launch_bounds__(256, 3)
asg_kernel(const float* __restrict__ x, const float* __restrict__ bc) {
    extern __shared__ char sm[];
    const int tid = threadIdx.x, lane = tid & 31, wid = tid >> 5;
    const int wm = wid & 3, wn = wid >> 2;
    const int row0 = blockIdx.x * 128, n = blockIdx.x >> 3;
    const int hw0 = row0 & (HW_ - 1);
    const uint32_t sb = smem_u32(sm);

    if (tid < 64) ((float*)(sm + BIAS1))[tid] = bc[tid];

    float acc[2][4][4];
#pragma unroll
    for (int a = 0; a < 2; a++)
#pragma unroll
        for (int b = 0; b < 4; b++)
#pragma unroll
            for (int c = 0; c < 4; c++) acc[a][b][c] = 0.f;

    const int arow = tid >> 1, aseg = (tid & 1) * 4;
    const int brow = tid >> 2, bseg = (tid & 3) * 16;

    for (int ch = 0; ch < 8; ch++) {
        // LDG -> split -> STS (no prefetch; occ-3 warps cover latency)
        {
            const float* xp = x + (size_t)(row0 + arow) * D_ + ch * 64 + aseg;
#pragma unroll
            for (int j = 0; j < 8; j++) {
                float4 v = *(const float4*)(xp + 8 * j);
                uint32_t h01, l01, h23, l23;
                split2(v.x, v.y, h01, l01);
                split2(v.z, v.w, h23, l23);
                uint32_t off = arow * RB + (aseg + 8 * j) * 2;
                *(uint2*)(sm + AH1 + off) = make_uint2(h01, h23);
                *(uint2*)(sm + AL1 + off) = make_uint2(l01, l23);
            }
            const unsigned short* wh = g_WTh + brow * D_ + ch * 64 + bseg;
            const unsigned short* wl = g_WTl + brow * D_ + ch * 64 + bseg;
            uint32_t boff = brow * RB + bseg * 2;
            *(uint4*)(sm + BH1 + boff) = *(const uint4*)wh;
            *(uint4*)(sm + BH1 + boff + 16) = *(const uint4*)(wh + 8);
            *(uint4*)(sm + BL1 + boff) = *(const uint4*)wl;
            *(uint4*)(sm + BL1 + boff + 16) = *(const uint4*)(wl + 8);
        }
        __syncthreads();
        // MMA
#pragma unroll
        for (int ks = 0; ks < 4; ks++) {
            uint32_t ah[2][4], al[2][4], bh[2][4], bl[2][4];
#pragma unroll
            for (int mt = 0; mt < 2; mt++) {
                uint32_t ad = sb + AH1 + (wm * 32 + mt * 16 + (lane & 15)) * RB
                              + (ks * 16 + (lane >> 4) * 8) * 2;
                ldm4(ah[mt], ad);
                ldm4(al[mt], ad + (AL1 - AH1));
            }
#pragma unroll
            for (int np = 0; np < 2; np++) {
                uint32_t bd = sb + BH1 +
                    (wn * 32 + np * 16 + (lane & 7) + ((lane >> 4) << 3)) * RB
                    + (ks * 16 + ((lane >> 3) & 1) * 8) * 2;
                ldm4(bh[np], bd);
                ldm4(bl[np], bd + (BL1 - BH1));
            }
#pragma unroll
            for (int mt = 0; mt < 2; mt++)
#pragma unroll
                for (int nt = 0; nt < 4; nt++) {
                    const uint32_t* bph = &bh[nt >> 1][(nt & 1) * 2];
                    const uint32_t* bpl = &bl[nt >> 1][(nt & 1) * 2];
                    mma16816(acc[mt][nt], ah[mt], bph);
                    mma16816(acc[mt][nt], ah[mt], bpl);
                    mma16816(acc[mt][nt], al[mt], bph);
                }
        }
        __syncthreads();
    }

    // scores -> SMEM s[128][66]
    float* s = (float*)sm;
#pragma unroll
    for (int mt = 0; mt < 2; mt++)
#pragma unroll
        for (int nt = 0; nt < 4; nt++) {
            int r = wm * 32 + mt * 16 + (lane >> 2);
            int col = wn * 32 + nt * 8 + 2 * (lane & 3);
            *(float2*)&s[r * 66 + col] = make_float2(acc[mt][nt][0], acc[mt][nt][1]);
            *(float2*)&s[(r + 8) * 66 + col] = make_float2(acc[mt][nt][2], acc[mt][nt][3]);
        }
    __syncthreads();

    if (tid < 128) {
        const float* bias = (const float*)(sm + BIAS1);
        float f[64];
        float m = -1e30f;
#pragma unroll
        for (int k = 0; k < 64; k++) { f[k] = s[tid * 66 + k] + bias[k]; m = fmaxf(m, f[k]); }
        float ssum = 0.f;
#pragma unroll
        for (int k = 0; k < 64; k++) { f[k] = fexp(f[k] - m); ssum += f[k]; }
        float inv = 1.0f / ssum;
#pragma unroll
        for (int k = 0; k < 64; k++) s[tid * 66 + k] = f[k] * inv;
    }
    __syncthreads();

    // coalesced a^T write: warp w -> k rows w*8..w*8+7, 128B runs per row
    {
        size_t nb = (size_t)n * K_ * HW_;
#pragma unroll
        for (int kk = 0; kk < 8; kk++) {
            int k = wid * 8 + kk;
#pragma unroll
            for (int half = 0; half < 2; half++) {
                int hw = half * 64 + 2 * lane;
                float a0 = s[hw * 66 + k];
                float a1 = s[(hw + 1) * 66 + k];
                uint32_t hp, lp;
                split2(a0, a1, hp, lp);
                size_t e = nb + (size_t)k * HW_ + hw0 + hw;
                *(uint32_t*)(g_aTh + e) = hp;
                *(uint32_t*)(g_aTl + e) = lp;
            }
        }
    }
    if (tid < 64) {
        float acc_s = 0.f;
#pragma unroll 8
        for (int r = 0; r < 128; r++) acc_s += s[r * 66 + tid];
        atomicAdd(&g_asum[n * K_ + tid], acc_s);
    }
}

// ================= GEMM2: V^T = a^T (64xHW) * x (HWx128d) ====================
// R9 structure: single buffer + register prefetch, occ 2
#define AH2 0
#define AL2 9216
#define BH2 18432
#define BL2 35840
#define AS2 53248
#define SMEM2 53504
#define VST 68       // v2 row stride in floats (272B, 16B-aligned)

__global__ void __launch_bounds__(256, 2)
vlad_kernel(const float* __restrict__ x, const float* __restrict__ Cc,
            float* __restrict__ out) {
    extern __shared__ char sm[];
    const int tid = threadIdx.x, lane = tid & 31, wid = tid >> 5;
    const int wm = wid & 1, wn = wid >> 1;
    const int n = blockIdx.y, m0 = blockIdx.x * 128;
    const uint32_t sb = smem_u32(sm);

    if (tid < 64) ((float*)(sm + AS2))[tid] = g_asum[n * K_ + tid];

    const float* xn = x + (size_t)n * HW_ * D_;
    const unsigned short* ath = g_aTh + (size_t)n * K_ * HW_;
    const unsigned short* atl = g_aTl + (size_t)n * K_ * HW_;

    float acc[2][4][4];
#pragma unroll
    for (int a = 0; a < 2; a++)
#pragma unroll
        for (int b = 0; b < 4; b++)
#pragma unroll
            for (int c = 0; c < 4; c++) acc[a][b][c] = 0.f;

    uint4 rah[2], ral[2];
    float4 rb[8];
    const int crow = tid >> 2, cseg = (tid & 3) * 16;
    const int xrow = tid >> 2, xseg = (tid & 3) * 4;

    // load chunk 0
    rah[0] = *(const uint4*)(ath + (size_t)crow * HW_ + cseg);
    rah[1] = *(const uint4*)(ath + (size_t)crow * HW_ + cseg + 8);
    ral[0] = *(const uint4*)(atl + (size_t)crow * HW_ + cseg);
    ral[1] = *(const uint4*)(atl + (size_t)crow * HW_ + cseg + 8);
#pragma unroll
    for (int j = 0; j < 8; j++)
        rb[j] = *(const float4*)(xn + (size_t)xrow * D_ + m0 + xseg + 16 * j);
    // store chunk 0
    *(uint4*)(sm + AH2 + crow * RB + cseg * 2) = rah[0];
    *(uint4*)(sm + AH2 + crow * RB + cseg * 2 + 16) = rah[1];
    *(uint4*)(sm + AL2 + crow * RB + cseg * 2) = ral[0];
    *(uint4*)(sm + AL2 + crow * RB + cseg * 2 + 16) = ral[1];
#pragma unroll
    for (int j = 0; j < 8; j++) {
        uint32_t h01, l01, h23, l23;
        split2(rb[j].x, rb[j].y, h01, l01);
        split2(rb[j].z, rb[j].w, h23, l23);
        uint32_t off = xrow * RB2 + (xseg + 16 * j) * 2;
        *(uint2*)(sm + BH2 + off) = make_uint2(h01, h23);
        *(uint2*)(sm + BL2 + off) = make_uint2(l01, l23);
    }
    __syncthreads();

    for (int ch = 0; ch < 16; ch++) {
        if (ch < 15) {   // prefetch next chunk into regs
            int hw1 = (ch + 1) * 64;
            const unsigned short* ah = ath + (size_t)crow * HW_ + hw1 + cseg;
            const unsigned short* al = atl + (size_t)crow * HW_ + hw1 + cseg;
            rah[0] = *(const uint4*)ah; rah[1] = *(const uint4*)(ah + 8);
            ral[0] = *(const uint4*)al; ral[1] = *(const uint4*)(al + 8);
            const float* xp = xn + (size_t)(hw1 + xrow) * D_ + m0 + xseg;
#pragma unroll
            for (int j = 0; j < 8; j++) rb[j] = *(const float4*)(xp + 16 * j);
        }
        // MMA on current tiles
#pragma unroll
        for (int ks = 0; ks < 4; ks++) {
            uint32_t ah[2][4], al[2][4], bh[2][4], bl[2][4];
#pragma unroll
            for (int mt = 0; mt < 2; mt++) {
                uint32_t ad = sb + AH2 + (wm * 32 + mt * 16 + (lane & 15)) * RB
                              + (ks * 16 + (lane >> 4) * 8) * 2;
                ldm4(ah[mt], ad);
                ldm4(al[mt], ad + (AL2 - AH2));
            }
#pragma unroll
            for (int np = 0; np < 2; np++) {
                uint32_t bd = sb + BH2 + (ks * 16 + (lane & 15)) * RB2
                              + (wn * 32 + np * 16 + (lane >> 4) * 8) * 2;
                ldm4t(bh[np], bd);
                ldm4t(bl[np], bd + (BL2 - BH2));
            }
#pragma unroll
            for (int mt = 0; mt < 2; mt++)
#pragma unroll
                for (int nt = 0; nt < 4; nt++) {
                    const uint32_t* bph = &bh[nt >> 1][(nt & 1) * 2];
                    const uint32_t* bpl = &bl[nt >> 1][(nt & 1) * 2];
                    mma16816(acc[mt][nt], ah[mt], bph);
                    mma16816(acc[mt][nt], ah[mt], bpl);
                    mma16816(acc[mt][nt], al[mt], bph);
                }
        }
        __syncthreads();
        if (ch < 15) {
            *(uint4*)(sm + AH2 + crow * RB + cseg * 2) = rah[0];
            *(uint4*)(sm + AH2 + crow * RB + cseg * 2 + 16) = rah[1];
            *(uint4*)(sm + AL2 + crow * RB + cseg * 2) = ral[0];
            *(uint4*)(sm + AL2 + crow * RB + cseg * 2 + 16) = ral[1];
#pragma unroll
            for (int j = 0; j < 8; j++) {
                uint32_t h01, l01, h23, l23;
                split2(rb[j].x, rb[j].y, h01, l01);
                split2(rb[j].z, rb[j].w, h23, l23);
                uint32_t off = xrow * RB2 + (xseg + 16 * j) * 2;
                *(uint2*)(sm + BH2 + off) = make_uint2(h01, h23);
                *(uint2*)(sm + BL2 + off) = make_uint2(l01, l23);
            }
            __syncthreads();
        }
    }

    // epilogue: acc (c,d) -> smem v2[d][VST] transposed
    float* v2 = (float*)sm;   // 128 x 68 f32 = 34816 B (aliases tiles)
#pragma unroll
    for (int mt = 0; mt < 2; mt++)
#pragma unroll
        for (int nt = 0; nt < 4; nt++) {
            int c = wm * 32 + mt * 16 + (lane >> 2);
            int d = wn * 32 + nt * 8 + 2 * (lane & 3);
            v2[d * VST + c] = acc[mt][nt][0];
            v2[(d + 1) * VST + c] = acc[mt][nt][1];
            v2[d * VST + c + 8] = acc[mt][nt][2];
            v2[(d + 1) * VST + c + 8] = acc[mt][nt][3];
        }
    __syncthreads();

    // output: +asum*C, coalesced store, o^2 back to v2 for colsq
    {
        const float* asums = (const float*)(sm + AS2);
        int d = tid >> 1, kh = (tid & 1) * 32;
        int dg = m0 + d;
        float* po = out + ((size_t)n * D_ + dg) * K_ + kh;
        const float* pc = Cc + (size_t)dg * K_ + kh;
#pragma unroll
        for (int j = 0; j < 8; j++) {
            float4 v = *(float4*)&v2[d * VST + kh + 4 * j];
            float4 cc = *(const float4*)(pc + 4 * j);
            float4 as = *(const float4*)(asums + kh + 4 * j);
            float4 o;
            o.x = fmaf(as.x, cc.x, v.x);
            o.y = fmaf(as.y, cc.y, v.y);
            o.z = fmaf(as.z, cc.z, v.z);
            o.w = fmaf(as.w, cc.w, v.w);
            *(float4*)(po + 4 * j) = o;
            float4 sq = make_float4(o.x * o.x, o.y * o.y, o.z * o.z, o.w * o.w);
            *(float4*)&v2[d * VST + kh + 4 * j] = sq;
        }
    }
    __syncthreads();
    if (tid < 64) {
        float s = 0.f;
#pragma unroll 8
        for (int d2 = 0; d2 < 128; d2++) s += v2[d2 * VST + tid];
        atomicAdd(&g_colsq[n * K_ + tid], s);
    }
}

// ---------------- norm -------------------------------------------------------
__global__ void norm2_kernel(float* __restrict__ out) {
    __shared__ float S[64];
    __shared__ float sc[64];
    __shared__ float gsh;
    const int n = blockIdx.y, tid = threadIdx.x;
    if (tid < 64) S[tid] = g_colsq[n * K_ + tid];
    __syncthreads();
    if (tid == 0) {
        float s = 0.f;
#pragma unroll
        for (int k = 0; k < 64; k++) s += S[k] / (S[k] + EPSF);
        gsh = rsqrtf(s + EPSF);
    }
    __syncthreads();
    if (tid < 64) sc[tid] = rsqrtf(S[tid] + EPSF) * gsh;
    __syncthreads();
    float* po = out + (size_t)n * D_ * K_ + blockIdx.x * 4096;
#pragma unroll
    for (int i = 0; i < 4; i++) {
        int e = tid * 4 + i * 1024;
        float4 v = *(float4*)(po + e);
        int k = e & 63;
        v.x *= sc[k + 0]; v.y *= sc[k + 1];
        v.z *= sc[k + 2]; v.w *= sc[k + 3];
        *(float4*)(po + e) = v;
    }
}

// ---------------------------------------------------------------------------
extern "C" void kernel_launch(void* const* d_in, const int* in_sizes, int n_in,
                              void* d_out, int out_size) {
    const float* x = (const float*)d_in[0];   // [64,32,32,512]
    const float* W = (const float*)d_in[1];   // [512,64]
    const float* b = (const float*)d_in[2];   // [64]
    const float* C = (const float*)d_in[3];   // [512,64]
    float* out = (float*)d_out;               // [64, 32768]

    cudaFuncSetAttribute(asg_kernel, cudaFuncAttributeMaxDynamicSharedMemorySize, SMEM1);
    cudaFuncSetAttribute(vlad_kernel, cudaFuncAttributeMaxDynamicSharedMemorySize, SMEM2);

    prep_kernel<<<128, 256>>>(W);
    asg_kernel<<<512, 256, SMEM1>>>(x, b);
    vlad_kernel<<<dim3(4, 64), 256, SMEM2>>>(x, C, out);
    norm2_kernel<<<dim3(8, 64), 256>>>(out);
}

// round 12
// speedup vs baseline: 1.1834x; 1.0132x over previous
#include <cuda_runtime.h>
#include <cuda_bf16.h>
#include <cstdint>

#define N_B 64
#define HW_ 1024
#define D_  512
#define K_  64
#define EPSF 1e-12f
#define RB   144     // A/B row bytes (72 bf16): ldmatrix conflict-free
#define RB2  272     // vlad B row bytes (136 bf16)

// ---------------- device scratch (allocation-free rule) ---------------------
__device__ unsigned short g_WTh[K_ * D_];                 // W^T hi bf16 [k][d]
__device__ unsigned short g_WTl[K_ * D_];                 // W^T lo bf16
__device__ unsigned short g_aTh[(size_t)N_B * K_ * HW_];  // a^T hi [n][k][hw]
__device__ unsigned short g_aTl[(size_t)N_B * K_ * HW_];  // a^T lo
__device__ float g_vp[(size_t)N_B * D_ * K_];             // vlad partial (hw half 1)
__device__ float g_asum[N_B * K_];
__device__ float g_colsq[N_B * K_];
__device__ float g_sc[N_B * K_];                          // final scale per (n,k)

// ---------------- helpers ----------------------------------------------------
__device__ __forceinline__ uint32_t smem_u32(const void* p) {
    uint32_t a;
    asm("{ .reg .u64 t; cvta.to.shared.u64 t, %1; cvt.u32.u64 %0, t; }"
        : "=r"(a) : "l"(p));
    return a;
}
__device__ __forceinline__ void ldm4(uint32_t* r, uint32_t a) {
    asm volatile("ldmatrix.sync.aligned.m8n8.x4.shared.b16 {%0,%1,%2,%3}, [%4];"
                 : "=r"(r[0]), "=r"(r[1]), "=r"(r[2]), "=r"(r[3]) : "r"(a));
}
__device__ __forceinline__ void ldm4t(uint32_t* r, uint32_t a) {
    asm volatile("ldmatrix.sync.aligned.m8n8.x4.trans.shared.b16 {%0,%1,%2,%3}, [%4];"
                 : "=r"(r[0]), "=r"(r[1]), "=r"(r[2]), "=r"(r[3]) : "r"(a));
}
__device__ __forceinline__ void mma16816(float* d, const uint32_t* a,
                                         const uint32_t* b) {
    asm volatile(
        "mma.sync.aligned.m16n8k16.row.col.f32.bf16.bf16.f32 "
        "{%0,%1,%2,%3}, {%4,%5,%6,%7}, {%8,%9}, {%0,%1,%2,%3};"
        : "+f"(d[0]), "+f"(d[1]), "+f"(d[2]), "+f"(d[3])
        : "r"(a[0]), "r"(a[1]), "r"(a[2]), "r"(a[3]), "r"(b[0]), "r"(b[1]));
}
__device__ __forceinline__ void split2(float x0, float x1, uint32_t& hp, uint32_t& lp) {
    uint32_t u0 = __float_as_uint(x0), u1 = __float_as_uint(x1);
    hp = __byte_perm(u0, u1, 0x7632);
    float l0 = x0 - __uint_as_float(u0 & 0xFFFF0000u);
    float l1 = x1 - __uint_as_float(u1 & 0xFFFF0000u);
    asm("cvt.rn.bf16x2.f32 %0, %1, %2;" : "=r"(lp) : "f"(l1), "f"(l0));
}
__device__ __forceinline__ float fexp(float x) {
    x = fmaxf(x, -80.0f);
    float t = x * 1.4426950408889634f;
    float tb = t + 12582912.0f;
    float f = t - (tb - 12582912.0f);
    int ei = __float_as_int(tb) - 0x4B400000;
    float p = 1.5403530e-4f;
    p = fmaf(p, f, 1.3333558e-3f);
    p = fmaf(p, f, 9.6181291e-3f);
    p = fmaf(p, f, 5.5504109e-2f);
    p = fmaf(p, f, 2.4022651e-1f);
    p = fmaf(p, f, 6.9314718e-1f);
    p = fmaf(p, f, 1.0f);
    return p * __int_as_float((ei + 127) << 23);
}

// ---------------- prep: W split + accumulator zeroing ------------------------
__global__ void prep_kernel(const float* __restrict__ W) {
    int t = blockIdx.x * blockDim.x + threadIdx.x;
    if (t < N_B * K_) { g_asum[t] = 0.f; g_colsq[t] = 0.f; }
    if (t < D_ * K_) {
        int d = t >> 6, k = t & 63;
        float w = W[t];
        uint32_t u = __float_as_uint(w);
        g_WTh[k * D_ + d] = (unsigned short)(u >> 16);
        float lo = w - __uint_as_float(u & 0xFFFF0000u);
        __nv_bfloat16 lb = __float2bfloat16(lo);
        g_WTl[k * D_ + d] = *reinterpret_cast<unsigned short*>(&lb);
    }
}

// ================= GEMM1: assignment + softmax (R9 proven version) ===========
#define AH1 0
#define AL1 18432
#define BH1 36864
#define BL1 46080
#define BIAS1 55296
#define SMEM1 55552

#define ASG_MMA()                                                              \
    do {                                                                       \
        _Pragma("unroll")                                                      \
        for (int ks = 0; ks < 4; ks++) {                                       \
            uint32_t ah[2][4], al[2][4], bh[2][4], bl[2][4];                   \
            _Pragma("unroll")                                                  \
            for (int mt = 0; mt < 2; mt++) {                                   \
                uint32_t ad = sb + AH1 + (wm * 32 + mt * 16 + (lane & 15)) * RB\
                              + (ks * 16 + (lane >> 4) * 8) * 2;               \
                ldm4(ah[mt], ad);                                              \
                ldm4(al[mt], ad + (AL1 - AH1));                                \
            }                                                                  \
            _Pragma("unroll")                                                  \
            for (int np = 0; np < 2; np++) {                                   \
                uint32_t bd = sb + BH1 +                                       \
                    (wn * 32 + np * 16 + (lane & 7) + ((lane >> 4) << 3)) * RB \
                    + (ks * 16 + ((lane >> 3) & 1) * 8) * 2;                   \
                ldm4(bh[np], bd);                                              \
                ldm4(bl[np], bd + (BL1 - BH1));                                \
            }                                                                  \
            _Pragma("unroll")                                                  \
            for (int mt = 0; mt < 2; mt++)                                     \
                _Pragma("unroll")                                              \
                for (int nt = 0; nt < 4; nt++) {                               \
                    const uint32_t* bph = &bh[nt >> 1][(nt & 1) * 2];          \
                    const uint32_t* bpl = &bl[nt >> 1][(nt & 1) * 2];          \
                    mma16816(acc[mt][nt], ah[mt], bph);                        \
                    mma16816(acc[mt][nt], ah[mt], bpl);                        \
                    mma16816(acc[mt][nt], al[mt], bph);                        \
                }                                                              \
        }                                                                      \
    } while (0)

__global__ void __launch_bounds__(256, 2)
asg_kernel(const float* __restrict__ x, const float* __restrict__ bc) {
    extern __shared__ char sm[];
    const int tid = threadIdx.x, lane = tid & 31, wid = tid >> 5;
    const int wm = wid & 3, wn = wid >> 2;
    const int row0 = blockIdx.x * 128, n = blockIdx.x >> 3;
    const int hw0 = row0 & (HW_ - 1);
    const uint32_t sb = smem_u32(sm);

    if (tid < 64) ((float*)(sm + BIAS1))[tid] = bc[tid];

    float acc[2][4][4];
#pragma unroll
    for (int a = 0; a < 2; a++)
#pragma unroll
        for (int b = 0; b < 4; b++)
#pragma unroll
            for (int c = 0; c < 4; c++) acc[a][b][c] = 0.f;

    float4 ra[8];
    uint4 rbh[2], rbl[2];
    const int arow = tid >> 1, aseg = (tid & 1) * 4;
    const int brow = tid >> 2, bseg = (tid & 3) * 16;

    // load chunk 0
#pragma unroll
    for (int j = 0; j < 8; j++)
        ra[j] = *(const float4*)(x + (size_t)(row0 + arow) * D_ + aseg + 8 * j);
    rbh[0] = *(const uint4*)(g_WTh + brow * D_ + bseg);
    rbh[1] = *(const uint4*)(g_WTh + brow * D_ + bseg + 8);
    rbl[0] = *(const uint4*)(g_WTl + brow * D_ + bseg);
    rbl[1] = *(const uint4*)(g_WTl + brow * D_ + bseg + 8);
    // store chunk 0
#pragma unroll
    for (int j = 0; j < 8; j++) {
        uint32_t h01, l01, h23, l23;
        split2(ra[j].x, ra[j].y, h01, l01);
        split2(ra[j].z, ra[j].w, h23, l23);
        uint32_t off = arow * RB + (aseg + 8 * j) * 2;
        *(uint2*)(sm + AH1 + off) = make_uint2(h01, h23);
        *(uint2*)(sm + AL1 + off) = make_uint2(l01, l23);
    }
    *(uint4*)(sm + BH1 + brow * RB + bseg * 2) = rbh[0];
    *(uint4*)(sm + BH1 + brow * RB + bseg * 2 + 16) = rbh[1];
    *(uint4*)(sm + BL1 + brow * RB + bseg * 2) = rbl[0];
    *(uint4*)(sm + BL1 + brow * RB + bseg * 2 + 16) = rbl[1];
    __syncthreads();

    for (int ch = 0; ch < 8; ch++) {
        if (ch < 7) {       // prefetch next chunk into regs (overlaps MMA)
            const float* xp = x + (size_t)(row0 + arow) * D_ + (ch + 1) * 64 + aseg;
#pragma unroll
            for (int j = 0; j < 8; j++) ra[j] = *(const float4*)(xp + 8 * j);
            const unsigned short* wh = g_WTh + brow * D_ + (ch + 1) * 64 + bseg;
            const unsigned short* wl = g_WTl + brow * D_ + (ch + 1) * 64 + bseg;
            rbh[0] = *(const uint4*)wh; rbh[1] = *(const uint4*)(wh + 8);
            rbl[0] = *(const uint4*)wl; rbl[1] = *(const uint4*)(wl + 8);
        }
        ASG_MMA();
        __syncthreads();
        if (ch < 7) {
#pragma unroll
            for (int j = 0; j < 8; j++) {
                uint32_t h01, l01, h23, l23;
                split2(ra[j].x, ra[j].y, h01, l01);
                split2(ra[j].z, ra[j].w, h23, l23);
                uint32_t off = arow * RB + (aseg + 8 * j) * 2;
                *(uint2*)(sm + AH1 + off) = make_uint2(h01, h23);
                *(uint2*)(sm + AL1 + off) = make_uint2(l01, l23);
            }
            *(uint4*)(sm + BH1 + brow * RB + bseg * 2) = rbh[0];
            *(uint4*)(sm + BH1 + brow * RB + bseg * 2 + 16) = rbh[1];
            *(uint4*)(sm + BL1 + brow * RB + bseg * 2) = rbl[0];
            *(uint4*)(sm + BL1 + brow * RB + bseg * 2 + 16) = rbl[1];
            __syncthreads();
        }
    }

    // scores -> SMEM s[128][66]
    float* s = (float*)sm;
#pragma unroll
    for (int mt = 0; mt < 2; mt++)
#pragma unroll
        for (int nt = 0; nt < 4; nt++) {
            int r = wm * 32 + mt * 16 + (lane >> 2);
            int col = wn * 32 + nt * 8 + 2 * (lane & 3);
            *(float2*)&s[r * 66 + col] = make_float2(acc[mt][nt][0], acc[mt][nt][1]);
            *(float2*)&s[(r + 8) * 66 + col] = make_float2(acc[mt][nt][2], acc[mt][nt][3]);
        }
    __syncthreads();

    if (tid < 128) {
        const float* bias = (const float*)(sm + BIAS1);
        float f[64];
        float m = -1e30f;
#pragma unroll
        for (int k = 0; k < 64; k++) { f[k] = s[tid * 66 + k] + bias[k]; m = fmaxf(m, f[k]); }
        float ssum = 0.f;
#pragma unroll
        for (int k = 0; k < 64; k++) { f[k] = fexp(f[k] - m); ssum += f[k]; }
        float inv = 1.0f / ssum;
#pragma unroll
        for (int k = 0; k < 64; k++) s[tid * 66 + k] = f[k] * inv;
    }
    __syncthreads();

    // coalesced a^T write
    {
        size_t nb = (size_t)n * K_ * HW_;
#pragma unroll
        for (int kk = 0; kk < 8; kk++) {
            int k = wid * 8 + kk;
#pragma unroll
            for (int half = 0; half < 2; half++) {
                int hw = half * 64 + 2 * lane;
                float a0 = s[hw * 66 + k];
                float a1 = s[(hw + 1) * 66 + k];
                uint32_t hp, lp;
                split2(a0, a1, hp, lp);
                size_t e = nb + (size_t)k * HW_ + hw0 + hw;
                *(uint32_t*)(g_aTh + e) = hp;
                *(uint32_t*)(g_aTl + e) = lp;
            }
        }
    }
    if (tid < 64) {
        float acc_s = 0.f;
#pragma unroll 8
        for (int r = 0; r < 128; r++) acc_s += s[r * 66 + tid];
        atomicAdd(&g_asum[n * K_ + tid], acc_s);
    }
}

// ================= GEMM2: V^T = a^T * x, split-K over hw halves ==============
#define AH2 0
#define AL2 9216
#define BH2 18432
#define BL2 35840
#define SMEM2 53248
#define VST 68       // v2 row stride in floats (272B, 16B-aligned)

__global__ void __launch_bounds__(256, 2)
vlad_kernel(const float* __restrict__ x, float* __restrict__ out) {
    extern __shared__ char sm[];
    const int tid = threadIdx.x, lane = tid & 31, wid = tid >> 5;
    const int wm = wid & 1, wn = wid >> 1;
    const int n = blockIdx.y, m0 = blockIdx.x * 128;
    const int hwb = blockIdx.z * 512;     // hw half base
    const uint32_t sb = smem_u32(sm);

    float* dst = blockIdx.z ? g_vp : out;

    const float* xn = x + (size_t)n * HW_ * D_;
    const unsigned short* ath = g_aTh + (size_t)n * K_ * HW_;
    const unsigned short* atl = g_aTl + (size_t)n * K_ * HW_;

    float acc[2][4][4];
#pragma unroll
    for (int a = 0; a < 2; a++)
#pragma unroll
        for (int b = 0; b < 4; b++)
#pragma unroll
            for (int c = 0; c < 4; c++) acc[a][b][c] = 0.f;

    uint4 rah[2], ral[2];
    float4 rb[8];
    const int crow = tid >> 2, cseg = (tid & 3) * 16;
    const int xrow = tid >> 2, xseg = (tid & 3) * 4;

    // load chunk 0
    rah[0] = *(const uint4*)(ath + (size_t)crow * HW_ + hwb + cseg);
    rah[1] = *(const uint4*)(ath + (size_t)crow * HW_ + hwb + cseg + 8);
    ral[0] = *(const uint4*)(atl + (size_t)crow * HW_ + hwb + cseg);
    ral[1] = *(const uint4*)(atl + (size_t)crow * HW_ + hwb + cseg + 8);
#pragma unroll
    for (int j = 0; j < 8; j++)
        rb[j] = *(const float4*)(xn + (size_t)(hwb + xrow) * D_ + m0 + xseg + 16 * j);
    // store chunk 0
    *(uint4*)(sm + AH2 + crow * RB + cseg * 2) = rah[0];
    *(uint4*)(sm + AH2 + crow * RB + cseg * 2 + 16) = rah[1];
    *(uint4*)(sm + AL2 + crow * RB + cseg * 2) = ral[0];
    *(uint4*)(sm + AL2 + crow * RB + cseg * 2 + 16) = ral[1];
#pragma unroll
    for (int j = 0; j < 8; j++) {
        uint32_t h01, l01, h23, l23;
        split2(rb[j].x, rb[j].y, h01, l01);
        split2(rb[j].z, rb[j].w, h23, l23);
        uint32_t off = xrow * RB2 + (xseg + 16 * j) * 2;
        *(uint2*)(sm + BH2 + off) = make_uint2(h01, h23);
        *(uint2*)(sm + BL2 + off) = make_uint2(l01, l23);
    }
    __syncthreads();

    for (int ch = 0; ch < 8; ch++) {
        if (ch < 7) {   // prefetch next chunk into regs
            int hw1 = hwb + (ch + 1) * 64;
            const unsigned short* ah = ath + (size_t)crow * HW_ + hw1 + cseg;
            const unsigned short* al = atl + (size_t)crow * HW_ + hw1 + cseg;
            rah[0] = *(const uint4*)ah; rah[1] = *(const uint4*)(ah + 8);
            ral[0] = *(const uint4*)al; ral[1] = *(const uint4*)(al + 8);
            const float* xp = xn + (size_t)(hw1 + xrow) * D_ + m0 + xseg;
#pragma unroll
            for (int j = 0; j < 8; j++) rb[j] = *(const float4*)(xp + 16 * j);
        }
        // MMA on current tiles
#pragma unroll
        for (int ks = 0; ks < 4; ks++) {
            uint32_t ah[2][4], al[2][4], bh[2][4], bl[2][4];
#pragma unroll
            for (int mt = 0; mt < 2; mt++) {
                uint32_t ad = sb + AH2 + (wm * 32 + mt * 16 + (lane & 15)) * RB
                              + (ks * 16 + (lane >> 4) * 8) * 2;
                ldm4(ah[mt], ad);
                ldm4(al[mt], ad + (AL2 - AH2));
            }
#pragma unroll
            for (int np = 0; np < 2; np++) {
                uint32_t bd = sb + BH2 + (ks * 16 + (lane & 15)) * RB2
                              + (wn * 32 + np * 16 + (lane >> 4) * 8) * 2;
                ldm4t(bh[np], bd);
                ldm4t(bl[np], bd + (BL2 - BH2));
            }
#pragma unroll
            for (int mt = 0; mt < 2; mt++)
#pragma unroll
                for (int nt = 0; nt < 4; nt++) {
                    const uint32_t* bph = &bh[nt >> 1][(nt & 1) * 2];
                    const uint32_t* bpl = &bl[nt >> 1][(nt & 1) * 2];
                    mma16816(acc[mt][nt], ah[mt], bph);
                    mma16816(acc[mt][nt], ah[mt], bpl);
                    mma16816(acc[mt][nt], al[mt], bph);
                }
        }
        __syncthreads();
        if (ch < 7) {
            *(uint4*)(sm + AH2 + crow * RB + cseg * 2) = rah[0];
            *(uint4*)(sm + AH2 + crow * RB + cseg * 2 + 16) = rah[1];
            *(uint4*)(sm + AL2 + crow * RB + cseg * 2) = ral[0];
            *(uint4*)(sm + AL2 + crow * RB + cseg * 2 + 16) = ral[1];
#pragma unroll
            for (int j = 0; j < 8; j++) {
                uint32_t h01, l01, h23, l23;
                split2(rb[j].x, rb[j].y, h01, l01);
                split2(rb[j].z, rb[j].w, h23, l23);
                uint32_t off = xrow * RB2 + (xseg + 16 * j) * 2;
                *(uint2*)(sm + BH2 + off) = make_uint2(h01, h23);
                *(uint2*)(sm + BL2 + off) = make_uint2(l01, l23);
            }
            __syncthreads();
        }
    }

    // epilogue: transpose acc via v2 then coalesced partial store (no C/colsq)
    float* v2 = (float*)sm;
#pragma unroll
    for (int mt = 0; mt < 2; mt++)
#pragma unroll
        for (int nt = 0; nt < 4; nt++) {
            int c = wm * 32 + mt * 16 + (lane >> 2);
            int d = wn * 32 + nt * 8 + 2 * (lane & 3);
            v2[d * VST + c] = acc[mt][nt][0];
            v2[(d + 1) * VST + c] = acc[mt][nt][1];
            v2[d * VST + c + 8] = acc[mt][nt][2];
            v2[(d + 1) * VST + c + 8] = acc[mt][nt][3];
        }
    __syncthreads();
    {
        int d = tid >> 1, kh = (tid & 1) * 32;
        float* po = dst + ((size_t)n * D_ + m0 + d) * K_ + kh;
#pragma unroll
        for (int j = 0; j < 8; j++)
            *(float4*)(po + 4 * j) = *(float4*)&v2[d * VST + kh + 4 * j];
    }
}

// ---------------- fixup: v = p0 + p1 + asum*C; colsq ---------------------------
__global__ void fixup_kernel(const float* __restrict__ Cc, float* __restrict__ out) {
    __shared__ float asm_s[64];
    __shared__ float red[16 * 65];
    const int n = blockIdx.y, d0 = blockIdx.x * 64;
    const int tid = threadIdx.x;
    const int drow = tid >> 4, k4 = (tid & 15) * 4;

    if (tid < 64) asm_s[tid] = g_asum[n * K_ + tid];
    __syncthreads();

    float4 as = *(const float4*)(asm_s + k4);
    float sq0 = 0.f, sq1 = 0.f, sq2 = 0.f, sq3 = 0.f;
#pragma unroll
    for (int it = 0; it < 4; it++) {
        int d = d0 + drow + it * 16;
        size_t idx = ((size_t)n * D_ + d) * K_ + k4;
        float4 v = *(const float4*)(out + idx);
        float4 p = *(const float4*)(g_vp + idx);
        float4 cc = *(const float4*)(Cc + (size_t)d * K_ + k4);
        float4 o;
        o.x = fmaf(as.x, cc.x, v.x + p.x);
        o.y = fmaf(as.y, cc.y, v.y + p.y);
        o.z = fmaf(as.z, cc.z, v.z + p.z);
        o.w = fmaf(as.w, cc.w, v.w + p.w);
        *(float4*)(out + idx) = o;
        sq0 = fmaf(o.x, o.x, sq0); sq1 = fmaf(o.y, o.y, sq1);
        sq2 = fmaf(o.z, o.z, sq2); sq3 = fmaf(o.w, o.w, sq3);
    }
    red[drow * 65 + k4 + 0] = sq0;
    red[drow * 65 + k4 + 1] = sq1;
    red[drow * 65 + k4 + 2] = sq2;
    red[drow * 65 + k4 + 3] = sq3;
    __syncthreads();
    if (tid < 64) {
        float s = 0.f;
#pragma unroll
        for (int r = 0; r < 16; r++) s += red[r * 65 + tid];
        atomicAdd(&g_colsq[n * K_ + tid], s);
    }
}

// ---------------- scale precompute --------------------------------------------
__global__ void scale_kernel() {
    __shared__ float contrib[64];
    __shared__ float gsh;
    const int n = blockIdx.x, t = threadIdx.x;
    float S = g_colsq[n * K_ + t];
    contrib[t] = S / (S + EPSF);
    __syncthreads();
    if (t == 0) {
        float g = 0.f;
#pragma unroll
        for (int k = 0; k < 64; k++) g += contrib[k];
        gsh = rsqrtf(g + EPSF);
    }
    __syncthreads();
    g_sc[n * K_ + t] = rsqrtf(S + EPSF) * gsh;
}

// ---------------- apply: pure streaming scale ----------------------------------
__global__ void apply_kernel(float* __restrict__ out) {
    __shared__ float sc[64];
    const int n = blockIdx.y, tid = threadIdx.x;
    if (tid < 64) sc[tid] = g_sc[n * K_ + tid];
    __syncthreads();
    float* po = out + (size_t)n * D_ * K_ + blockIdx.x * 2048;
#pragma unroll
    for (int i = 0; i < 2; i++) {
        int e = tid * 4 + i * 1024;
        float4 v = *(float4*)(po + e);
        int k = e & 63;
        v.x *= sc[k + 0]; v.y *= sc[k + 1];
        v.z *= sc[k + 2]; v.w *= sc[k + 3];
        *(float4*)(po + e) = v;
    }
}

// ---------------------------------------------------------------------------
extern "C" void kernel_launch(void* const* d_in, const int* in_sizes, int n_in,
                              void* d_out, int out_size) {
    const float* x = (const float*)d_in[0];   // [64,32,32,512]
    const float* W = (const float*)d_in[1];   // [512,64]
    const float* b = (const float*)d_in[2];   // [64]
    const float* C = (const float*)d_in[3];   // [512,64]
    float* out = (float*)d_out;               // [64, 32768]

    cudaFuncSetAttribute(asg_kernel, cudaFuncAttributeMaxDynamicSharedMemorySize, SMEM1);
    cudaFuncSetAttribute(vlad_kernel, cudaFuncAttributeMaxDynamicSharedMemorySize, SMEM2);

    prep_kernel<<<128, 256>>>(W);
    asg_kernel<<<512, 256, SMEM1>>>(x, b);
    vlad_kernel<<<dim3(4, 64, 2), 256, SMEM2>>>(x, out);
    fixup_kernel<<<dim3(8, 64), 256>>>(C, out);
    scale_kernel<<<64, 64>>>();
    apply_kernel<<<dim3(16, 64), 256>>>(out);
}

// round 13
// speedup vs baseline: 1.2402x; 1.0479x over previous
#include <cuda_runtime.h>
#include <cuda_bf16.h>
#include <cstdint>

#define N_B 64
#define HW_ 1024
#define D_  512
#define K_  64
#define EPSF 1e-12f
#define RB   144     // A/B row bytes (72 bf16): ldmatrix conflict-free
#define RB2  272     // vlad B row bytes (136 bf16)

// ---------------- device scratch (allocation-free rule) ---------------------
__device__ unsigned short g_WTh[K_ * D_];                 // W^T hi bf16 [k][d]
__device__ unsigned short g_WTl[K_ * D_];                 // W^T lo bf16
__device__ unsigned short g_aTh[(size_t)N_B * K_ * HW_];  // a^T hi [n][k][hw]
__device__ unsigned short g_aTl[(size_t)N_B * K_ * HW_];  // a^T lo
__device__ float g_asum[N_B * K_];
__device__ float g_colsq[N_B * K_];
__device__ float g_sc[N_B * K_];                          // final scale per (n,k)

// ---------------- helpers ----------------------------------------------------
__device__ __forceinline__ uint32_t smem_u32(const void* p) {
    uint32_t a;
    asm("{ .reg .u64 t; cvta.to.shared.u64 t, %1; cvt.u32.u64 %0, t; }"
        : "=r"(a) : "l"(p));
    return a;
}
__device__ __forceinline__ void ldm4(uint32_t* r, uint32_t a) {
    asm volatile("ldmatrix.sync.aligned.m8n8.x4.shared.b16 {%0,%1,%2,%3}, [%4];"
                 : "=r"(r[0]), "=r"(r[1]), "=r"(r[2]), "=r"(r[3]) : "r"(a));
}
__device__ __forceinline__ void ldm4t(uint32_t* r, uint32_t a) {
    asm volatile("ldmatrix.sync.aligned.m8n8.x4.trans.shared.b16 {%0,%1,%2,%3}, [%4];"
                 : "=r"(r[0]), "=r"(r[1]), "=r"(r[2]), "=r"(r[3]) : "r"(a));
}
__device__ __forceinline__ void mma16816(float* d, const uint32_t* a,
                                         const uint32_t* b) {
    asm volatile(
        "mma.sync.aligned.m16n8k16.row.col.f32.bf16.bf16.f32 "
        "{%0,%1,%2,%3}, {%4,%5,%6,%7}, {%8,%9}, {%0,%1,%2,%3};"
        : "+f"(d[0]), "+f"(d[1]), "+f"(d[2]), "+f"(d[3])
        : "r"(a[0]), "r"(a[1]), "r"(a[2]), "r"(a[3]), "r"(b[0]), "r"(b[1]));
}
__device__ __forceinline__ void split2(float x0, float x1, uint32_t& hp, uint32_t& lp) {
    uint32_t u0 = __float_as_uint(x0), u1 = __float_as_uint(x1);
    hp = __byte_perm(u0, u1, 0x7632);
    float l0 = x0 - __uint_as_float(u0 & 0xFFFF0000u);
    float l1 = x1 - __uint_as_float(u1 & 0xFFFF0000u);
    asm("cvt.rn.bf16x2.f32 %0, %1, %2;" : "=r"(lp) : "f"(l1), "f"(l0));
}
__device__ __forceinline__ float fexp(float x) {
    x = fmaxf(x, -80.0f);
    float t = x * 1.4426950408889634f;
    float tb = t + 12582912.0f;
    float f = t - (tb - 12582912.0f);
    int ei = __float_as_int(tb) - 0x4B400000;
    float p = 1.5403530e-4f;
    p = fmaf(p, f, 1.3333558e-3f);
    p = fmaf(p, f, 9.6181291e-3f);
    p = fmaf(p, f, 5.5504109e-2f);
    p = fmaf(p, f, 2.4022651e-1f);
    p = fmaf(p, f, 6.9314718e-1f);
    p = fmaf(p, f, 1.0f);
    return p * __int_as_float((ei + 127) << 23);
}

// ---------------- prep: W split + accumulator zeroing ------------------------
__global__ void prep_kernel(const float* __restrict__ W) {
    int t = blockIdx.x * blockDim.x + threadIdx.x;
    if (t < N_B * K_) { g_asum[t] = 0.f; g_colsq[t] = 0.f; }
    if (t < D_ * K_) {
        int d = t >> 6, k = t & 63;
        float w = W[t];
        uint32_t u = __float_as_uint(w);
        g_WTh[k * D_ + d] = (unsigned short)(u >> 16);
        float lo = w - __uint_as_float(u & 0xFFFF0000u);
        __nv_bfloat16 lb = __float2bfloat16(lo);
        g_WTl[k * D_ + d] = *reinterpret_cast<unsigned short*>(&lb);
    }
}

// ================= GEMM1: assignment + softmax (R9 proven version) ===========
#define AH1 0
#define AL1 18432
#define BH1 36864
#define BL1 46080
#define BIAS1 55296
#define SMEM1 55552

#define ASG_MMA()                                                              \
    do {                                                                       \
        _Pragma("unroll")                                                      \
        for (int ks = 0; ks < 4; ks++) {                                       \
            uint32_t ah[2][4], al[2][4], bh[2][4], bl[2][4];                   \
            _Pragma("unroll")                                                  \
            for (int mt = 0; mt < 2; mt++) {                                   \
                uint32_t ad = sb + AH1 + (wm * 32 + mt * 16 + (lane & 15)) * RB\
                              + (ks * 16 + (lane >> 4) * 8) * 2;               \
                ldm4(ah[mt], ad);                                              \
                ldm4(al[mt], ad + (AL1 - AH1));                                \
            }                                                                  \
            _Pragma("unroll")                                                  \
            for (int np = 0; np < 2; np++) {                                   \
                uint32_t bd = sb + BH1 +                                       \
                    (wn * 32 + np * 16 + (lane & 7) + ((lane >> 4) << 3)) * RB \
                    + (ks * 16 + ((lane >> 3) & 1) * 8) * 2;                   \
                ldm4(bh[np], bd);                                              \
                ldm4(bl[np], bd + (BL1 - BH1));                                \
            }                                                                  \
            _Pragma("unroll")                                                  \
            for (int mt = 0; mt < 2; mt++)                                     \
                _Pragma("unroll")                                              \
                for (int nt = 0; nt < 4; nt++) {                               \
                    const uint32_t* bph = &bh[nt >> 1][(nt & 1) * 2];          \
                    const uint32_t* bpl = &bl[nt >> 1][(nt & 1) * 2];          \
                    mma16816(acc[mt][nt], ah[mt], bph);                        \
                    mma16816(acc[mt][nt], ah[mt], bpl);                        \
                    mma16816(acc[mt][nt], al[mt], bph);                        \
                }                                                              \
        }                                                                      \
    } while (0)

__global__ void __launch_bounds__(256, 2)
asg_kernel(const float* __restrict__ x, const float* __restrict__ bc) {
    extern __shared__ char sm[];
    const int tid = threadIdx.x, lane = tid & 31, wid = tid >> 5;
    const int wm = wid & 3, wn = wid >> 2;
    const int row0 = blockIdx.x * 128, n = blockIdx.x >> 3;
    const int hw0 = row0 & (HW_ - 1);
    const uint32_t sb = smem_u32(sm);

    if (tid < 64) ((float*)(sm + BIAS1))[tid] = bc[tid];

    float acc[2][4][4];
#pragma unroll
    for (int a = 0; a < 2; a++)
#pragma unroll
        for (int b = 0; b < 4; b++)
#pragma unroll
            for (int c = 0; c < 4; c++) acc[a][b][c] = 0.f;

    float4 ra[8];
    uint4 rbh[2], rbl[2];
    const int arow = tid >> 1, aseg = (tid & 1) * 4;
    const int brow = tid >> 2, bseg = (tid & 3) * 16;

    // load chunk 0
#pragma unroll
    for (int j = 0; j < 8; j++)
        ra[j] = *(const float4*)(x + (size_t)(row0 + arow) * D_ + aseg + 8 * j);
    rbh[0] = *(const uint4*)(g_WTh + brow * D_ + bseg);
    rbh[1] = *(const uint4*)(g_WTh + brow * D_ + bseg + 8);
    rbl[0] = *(const uint4*)(g_WTl + brow * D_ + bseg);
    rbl[1] = *(const uint4*)(g_WTl + brow * D_ + bseg + 8);
    // store chunk 0
#pragma unroll
    for (int j = 0; j < 8; j++) {
        uint32_t h01, l01, h23, l23;
        split2(ra[j].x, ra[j].y, h01, l01);
        split2(ra[j].z, ra[j].w, h23, l23);
        uint32_t off = arow * RB + (aseg + 8 * j) * 2;
        *(uint2*)(sm + AH1 + off) = make_uint2(h01, h23);
        *(uint2*)(sm + AL1 + off) = make_uint2(l01, l23);
    }
    *(uint4*)(sm + BH1 + brow * RB + bseg * 2) = rbh[0];
    *(uint4*)(sm + BH1 + brow * RB + bseg * 2 + 16) = rbh[1];
    *(uint4*)(sm + BL1 + brow * RB + bseg * 2) = rbl[0];
    *(uint4*)(sm + BL1 + brow * RB + bseg * 2 + 16) = rbl[1];
    __syncthreads();

    for (int ch = 0; ch < 8; ch++) {
        if (ch < 7) {       // prefetch next chunk into regs (overlaps MMA)
            const float* xp = x + (size_t)(row0 + arow) * D_ + (ch + 1) * 64 + aseg;
#pragma unroll
            for (int j = 0; j < 8; j++) ra[j] = *(const float4*)(xp + 8 * j);
            const unsigned short* wh = g_WTh + brow * D_ + (ch + 1) * 64 + bseg;
            const unsigned short* wl = g_WTl + brow * D_ + (ch + 1) * 64 + bseg;
            rbh[0] = *(const uint4*)wh; rbh[1] = *(const uint4*)(wh + 8);
            rbl[0] = *(const uint4*)wl; rbl[1] = *(const uint4*)(wl + 8);
        }
        ASG_MMA();
        __syncthreads();
        if (ch < 7) {
#pragma unroll
            for (int j = 0; j < 8; j++) {
                uint32_t h01, l01, h23, l23;
                split2(ra[j].x, ra[j].y, h01, l01);
                split2(ra[j].z, ra[j].w, h23, l23);
                uint32_t off = arow * RB + (aseg + 8 * j) * 2;
                *(uint2*)(sm + AH1 + off) = make_uint2(h01, h23);
                *(uint2*)(sm + AL1 + off) = make_uint2(l01, l23);
            }
            *(uint4*)(sm + BH1 + brow * RB + bseg * 2) = rbh[0];
            *(uint4*)(sm + BH1 + brow * RB + bseg * 2 + 16) = rbh[1];
            *(uint4*)(sm + BL1 + brow * RB + bseg * 2) = rbl[0];
            *(uint4*)(sm + BL1 + brow * RB + bseg * 2 + 16) = rbl[1];
            __syncthreads();
        }
    }

    // scores -> SMEM s[128][66]
    float* s = (float*)sm;
#pragma unroll
    for (int mt = 0; mt < 2; mt++)
#pragma unroll
        for (int nt = 0; nt < 4; nt++) {
            int r = wm * 32 + mt * 16 + (lane >> 2);
            int col = wn * 32 + nt * 8 + 2 * (lane & 3);
            *(float2*)&s[r * 66 + col] = make_float2(acc[mt][nt][0], acc[mt][nt][1]);
            *(float2*)&s[(r + 8) * 66 + col] = make_float2(acc[mt][nt][2], acc[mt][nt][3]);
        }
    __syncthreads();

    if (tid < 128) {
        const float* bias = (const float*)(sm + BIAS1);
        float f[64];
        float m = -1e30f;
#pragma unroll
        for (int k = 0; k < 64; k++) { f[k] = s[tid * 66 + k] + bias[k]; m = fmaxf(m, f[k]); }
        float ssum = 0.f;
#pragma unroll
        for (int k = 0; k < 64; k++) { f[k] = fexp(f[k] - m); ssum += f[k]; }
        float inv = 1.0f / ssum;
#pragma unroll
        for (int k = 0; k < 64; k++) s[tid * 66 + k] = f[k] * inv;
    }
    __syncthreads();

    // coalesced a^T write
    {
        size_t nb = (size_t)n * K_ * HW_;
#pragma unroll
        for (int kk = 0; kk < 8; kk++) {
            int k = wid * 8 + kk;
#pragma unroll
            for (int half = 0; half < 2; half++) {
                int hw = half * 64 + 2 * lane;
                float a0 = s[hw * 66 + k];
                float a1 = s[(hw + 1) * 66 + k];
                uint32_t hp, lp;
                split2(a0, a1, hp, lp);
                size_t e = nb + (size_t)k * HW_ + hw0 + hw;
                *(uint32_t*)(g_aTh + e) = hp;
                *(uint32_t*)(g_aTl + e) = lp;
            }
        }
    }
    if (tid < 64) {
        float acc_s = 0.f;
#pragma unroll 8
        for (int r = 0; r < 128; r++) acc_s += s[r * 66 + tid];
        atomicAdd(&g_asum[n * K_ + tid], acc_s);
    }
}

// ================= GEMM2: V^T = a^T (64xHW) * x (HWx128d), R9 version ========
#define AH2 0
#define AL2 9216
#define BH2 18432
#define BL2 35840
#define AS2 53248
#define SMEM2 53504
#define VST 68       // v2 row stride in floats (272B, 16B-aligned)

__global__ void __launch_bounds__(256, 2)
vlad_kernel(const float* __restrict__ x, const float* __restrict__ Cc,
            float* __restrict__ out) {
    extern __shared__ char sm[];
    const int tid = threadIdx.x, lane = tid & 31, wid = tid >> 5;
    const int wm = wid & 1, wn = wid >> 1;
    const int n = blockIdx.y, m0 = blockIdx.x * 128;
    const uint32_t sb = smem_u32(sm);

    if (tid < 64) ((float*)(sm + AS2))[tid] = g_asum[n * K_ + tid];

    const float* xn = x + (size_t)n * HW_ * D_;
    const unsigned short* ath = g_aTh + (size_t)n * K_ * HW_;
    const unsigned short* atl = g_aTl + (size_t)n * K_ * HW_;

    float acc[2][4][4];
#pragma unroll
    for (int a = 0; a < 2; a++)
#pragma unroll
        for (int b = 0; b < 4; b++)
#pragma unroll
            for (int c = 0; c < 4; c++) acc[a][b][c] = 0.f;

    uint4 rah[2], ral[2];
    float4 rb[8];
    const int crow = tid >> 2, cseg = (tid & 3) * 16;
    const int xrow = tid >> 2, xseg = (tid & 3) * 4;

    // load chunk 0
    rah[0] = *(const uint4*)(ath + (size_t)crow * HW_ + cseg);
    rah[1] = *(const uint4*)(ath + (size_t)crow * HW_ + cseg + 8);
    ral[0] = *(const uint4*)(atl + (size_t)crow * HW_ + cseg);
    ral[1] = *(const uint4*)(atl + (size_t)crow * HW_ + cseg + 8);
#pragma unroll
    for (int j = 0; j < 8; j++)
        rb[j] = *(const float4*)(xn + (size_t)xrow * D_ + m0 + xseg + 16 * j);
    // store chunk 0
    *(uint4*)(sm + AH2 + crow * RB + cseg * 2) = rah[0];
    *(uint4*)(sm + AH2 + crow * RB + cseg * 2 + 16) = rah[1];
    *(uint4*)(sm + AL2 + crow * RB + cseg * 2) = ral[0];
    *(uint4*)(sm + AL2 + crow * RB + cseg * 2 + 16) = ral[1];
#pragma unroll
    for (int j = 0; j < 8; j++) {
        uint32_t h01, l01, h23, l23;
        split2(rb[j].x, rb[j].y, h01, l01);
        split2(rb[j].z, rb[j].w, h23, l23);
        uint32_t off = xrow * RB2 + (xseg + 16 * j) * 2;
        *(uint2*)(sm + BH2 + off) = make_uint2(h01, h23);
        *(uint2*)(sm + BL2 + off) = make_uint2(l01, l23);
    }
    __syncthreads();

    for (int ch = 0; ch < 16; ch++) {
        if (ch < 15) {   // prefetch next chunk into regs
            int hw1 = (ch + 1) * 64;
            const unsigned short* ah = ath + (size_t)crow * HW_ + hw1 + cseg;
            const unsigned short* al = atl + (size_t)crow * HW_ + hw1 + cseg;
            rah[0] = *(const uint4*)ah; rah[1] = *(const uint4*)(ah + 8);
            ral[0] = *(const uint4*)al; ral[1] = *(const uint4*)(al + 8);
            const float* xp = xn + (size_t)(hw1 + xrow) * D_ + m0 + xseg;
#pragma unroll
            for (int j = 0; j < 8; j++) rb[j] = *(const float4*)(xp + 16 * j);
        }
        // MMA on current tiles
#pragma unroll
        for (int ks = 0; ks < 4; ks++) {
            uint32_t ah[2][4], al[2][4], bh[2][4], bl[2][4];
#pragma unroll
            for (int mt = 0; mt < 2; mt++) {
                uint32_t ad = sb + AH2 + (wm * 32 + mt * 16 + (lane & 15)) * RB
                              + (ks * 16 + (lane >> 4) * 8) * 2;
                ldm4(ah[mt], ad);
                ldm4(al[mt], ad + (AL2 - AH2));
            }
#pragma unroll
            for (int np = 0; np < 2; np++) {
                uint32_t bd = sb + BH2 + (ks * 16 + (lane & 15)) * RB2
                              + (wn * 32 + np * 16 + (lane >> 4) * 8) * 2;
                ldm4t(bh[np], bd);
                ldm4t(bl[np], bd + (BL2 - BH2));
            }
#pragma unroll
            for (int mt = 0; mt < 2; mt++)
#pragma unroll
                for (int nt = 0; nt < 4; nt++) {
                    const uint32_t* bph = &bh[nt >> 1][(nt & 1) * 2];
                    const uint32_t* bpl = &bl[nt >> 1][(nt & 1) * 2];
                    mma16816(acc[mt][nt], ah[mt], bph);
                    mma16816(acc[mt][nt], ah[mt], bpl);
                    mma16816(acc[mt][nt], al[mt], bph);
                }
        }
        __syncthreads();
        if (ch < 15) {
            *(uint4*)(sm + AH2 + crow * RB + cseg * 2) = rah[0];
            *(uint4*)(sm + AH2 + crow * RB + cseg * 2 + 16) = rah[1];
            *(uint4*)(sm + AL2 + crow * RB + cseg * 2) = ral[0];
            *(uint4*)(sm + AL2 + crow * RB + cseg * 2 + 16) = ral[1];
#pragma unroll
            for (int j = 0; j < 8; j++) {
                uint32_t h01, l01, h23, l23;
                split2(rb[j].x, rb[j].y, h01, l01);
                split2(rb[j].z, rb[j].w, h23, l23);
                uint32_t off = xrow * RB2 + (xseg + 16 * j) * 2;
                *(uint2*)(sm + BH2 + off) = make_uint2(h01, h23);
                *(uint2*)(sm + BL2 + off) = make_uint2(l01, l23);
            }
            __syncthreads();
        }
    }

    // epilogue: acc (c,d) -> smem v2[d][VST] transposed
    float* v2 = (float*)sm;
#pragma unroll
    for (int mt = 0; mt < 2; mt++)
#pragma unroll
        for (int nt = 0; nt < 4; nt++) {
            int c = wm * 32 + mt * 16 + (lane >> 2);
            int d = wn * 32 + nt * 8 + 2 * (lane & 3);
            v2[d * VST + c] = acc[mt][nt][0];
            v2[(d + 1) * VST + c] = acc[mt][nt][1];
            v2[d * VST + c + 8] = acc[mt][nt][2];
            v2[(d + 1) * VST + c + 8] = acc[mt][nt][3];
        }
    __syncthreads();

    // output: +asum*C, coalesced store, o^2 back to v2 for colsq
    {
        const float* asums = (const float*)(sm + AS2);
        int d = tid >> 1, kh = (tid & 1) * 32;
        int dg = m0 + d;
        float* po = out + ((size_t)n * D_ + dg) * K_ + kh;
        const float* pc = Cc + (size_t)dg * K_ + kh;
#pragma unroll
        for (int j = 0; j < 8; j++) {
            float4 v = *(float4*)&v2[d * VST + kh + 4 * j];
            float4 cc = *(const float4*)(pc + 4 * j);
            float4 as = *(const float4*)(asums + kh + 4 * j);
            float4 o;
            o.x = fmaf(as.x, cc.x, v.x);
            o.y = fmaf(as.y, cc.y, v.y);
            o.z = fmaf(as.z, cc.z, v.z);
            o.w = fmaf(as.w, cc.w, v.w);
            *(float4*)(po + 4 * j) = o;
            float4 sq = make_float4(o.x * o.x, o.y * o.y, o.z * o.z, o.w * o.w);
            *(float4*)&v2[d * VST + kh + 4 * j] = sq;
        }
    }
    __syncthreads();
    if (tid < 64) {
        float s = 0.f;
#pragma unroll 8
        for (int d2 = 0; d2 < 128; d2++) s += v2[d2 * VST + tid];
        atomicAdd(&g_colsq[n * K_ + tid], s);
    }
}

// ---------------- scale precompute (tiny, per-n) -----------------------------
__global__ void scale_kernel() {
    __shared__ float contrib[64];
    __shared__ float gsh;
    const int n = blockIdx.x, t = threadIdx.x;
    float S = g_colsq[n * K_ + t];
    contrib[t] = S / (S + EPSF);
    __syncthreads();
    if (t == 0) {
        float g = 0.f;
#pragma unroll
        for (int k = 0; k < 64; k++) g += contrib[k];
        gsh = rsqrtf(g + EPSF);
    }
    __syncthreads();
    g_sc[n * K_ + t] = rsqrtf(S + EPSF) * gsh;
}

// ---------------- apply: pure streaming scale --------------------------------
__global__ void apply_kernel(float* __restrict__ out) {
    __shared__ float sc[64];
    const int n = blockIdx.y, tid = threadIdx.x;
    if (tid < 64) sc[tid] = g_sc[n * K_ + tid];
    __syncthreads();
    float* po = out + (size_t)n * D_ * K_ + blockIdx.x * 2048;
#pragma unroll
    for (int i = 0; i < 2; i++) {
        int e = tid * 4 + i * 1024;
        float4 v = *(float4*)(po + e);
        int k = e & 63;
        v.x *= sc[k + 0]; v.y *= sc[k + 1];
        v.z *= sc[k + 2]; v.w *= sc[k + 3];
        *(float4*)(po + e) = v;
    }
}

// ---------------------------------------------------------------------------
extern "C" void kernel_launch(void* const* d_in, const int* in_sizes, int n_in,
                              void* d_out, int out_size) {
    const float* x = (const float*)d_in[0];   // [64,32,32,512]
    const float* W = (const float*)d_in[1];   // [512,64]
    const float* b = (const float*)d_in[2];   // [64]
    const float* C = (const float*)d_in[3];   // [512,64]
    float* out = (float*)d_out;               // [64, 32768]

    cudaFuncSetAttribute(asg_kernel, cudaFuncAttributeMaxDynamicSharedMemorySize, SMEM1);
    cudaFuncSetAttribute(vlad_kernel, cudaFuncAttributeMaxDynamicSharedMemorySize, SMEM2);

    prep_kernel<<<128, 256>>>(W);
    asg_kernel<<<512, 256, SMEM1>>>(x, b);
    vlad_kernel<<<dim3(4, 64), 256, SMEM2>>>(x, C, out);
    scale_kernel<<<64, 64>>>();
    apply_kernel<<<dim3(16, 64), 256>>>(out);
}

// round 14
// speedup vs baseline: 1.2546x; 1.0117x over previous
#include <cuda_runtime.h>
#include <cuda_bf16.h>
#include <cstdint>

#define N_B 64
#define HW_ 1024
#define D_  512
#define K_  64
#define EPSF 1e-12f
#define RB   144     // A/B row bytes (72 bf16): ldmatrix conflict-free
#define RB2  272     // vlad B row bytes (136 bf16)

// ---------------- device scratch (allocation-free rule) ---------------------
__device__ unsigned short g_WTh[K_ * D_];                 // W^T hi bf16 [k][d]
__device__ unsigned short g_WTl[K_ * D_];                 // W^T lo bf16
__device__ unsigned short g_aTh[(size_t)N_B * K_ * HW_];  // a^T hi [n][k][hw]
__device__ unsigned short g_aTl[(size_t)N_B * K_ * HW_];  // a^T lo
__device__ float g_asum[N_B * K_];
__device__ float g_colsq[N_B * K_];

// ---------------- helpers ----------------------------------------------------
__device__ __forceinline__ uint32_t smem_u32(const void* p) {
    uint32_t a;
    asm("{ .reg .u64 t; cvta.to.shared.u64 t, %1; cvt.u32.u64 %0, t; }"
        : "=r"(a) : "l"(p));
    return a;
}
__device__ __forceinline__ void ldm4(uint32_t* r, uint32_t a) {
    asm volatile("ldmatrix.sync.aligned.m8n8.x4.shared.b16 {%0,%1,%2,%3}, [%4];"
                 : "=r"(r[0]), "=r"(r[1]), "=r"(r[2]), "=r"(r[3]) : "r"(a));
}
__device__ __forceinline__ void ldm4t(uint32_t* r, uint32_t a) {
    asm volatile("ldmatrix.sync.aligned.m8n8.x4.trans.shared.b16 {%0,%1,%2,%3}, [%4];"
                 : "=r"(r[0]), "=r"(r[1]), "=r"(r[2]), "=r"(r[3]) : "r"(a));
}
__device__ __forceinline__ void mma16816(float* d, const uint32_t* a,
                                         const uint32_t* b) {
    asm volatile(
        "mma.sync.aligned.m16n8k16.row.col.f32.bf16.bf16.f32 "
        "{%0,%1,%2,%3}, {%4,%5,%6,%7}, {%8,%9}, {%0,%1,%2,%3};"
        : "+f"(d[0]), "+f"(d[1]), "+f"(d[2]), "+f"(d[3])
        : "r"(a[0]), "r"(a[1]), "r"(a[2]), "r"(a[3]), "r"(b[0]), "r"(b[1]));
}
__device__ __forceinline__ void split2(float x0, float x1, uint32_t& hp, uint32_t& lp) {
    uint32_t u0 = __float_as_uint(x0), u1 = __float_as_uint(x1);
    hp = __byte_perm(u0, u1, 0x7632);
    float l0 = x0 - __uint_as_float(u0 & 0xFFFF0000u);
    float l1 = x1 - __uint_as_float(u1 & 0xFFFF0000u);
    asm("cvt.rn.bf16x2.f32 %0, %1, %2;" : "=r"(lp) : "f"(l1), "f"(l0));
}
__device__ __forceinline__ float fexp(float x) {
    x = fmaxf(x, -80.0f);
    float t = x * 1.4426950408889634f;
    float tb = t + 12582912.0f;
    float f = t - (tb - 12582912.0f);
    int ei = __float_as_int(tb) - 0x4B400000;
    float p = 1.5403530e-4f;
    p = fmaf(p, f, 1.3333558e-3f);
    p = fmaf(p, f, 9.6181291e-3f);
    p = fmaf(p, f, 5.5504109e-2f);
    p = fmaf(p, f, 2.4022651e-1f);
    p = fmaf(p, f, 6.9314718e-1f);
    p = fmaf(p, f, 1.0f);
    return p * __int_as_float((ei + 127) << 23);
}

// ---------------- prep: W split + accumulator zeroing ------------------------
__global__ void prep_kernel(const float* __restrict__ W) {
    int t = blockIdx.x * blockDim.x + threadIdx.x;
    if (t < N_B * K_) { g_asum[t] = 0.f; g_colsq[t] = 0.f; }
    if (t < D_ * K_) {
        int d = t >> 6, k = t & 63;
        float w = W[t];
        uint32_t u = __float_as_uint(w);
        g_WTh[k * D_ + d] = (unsigned short)(u >> 16);
        float lo = w - __uint_as_float(u & 0xFFFF0000u);
        __nv_bfloat16 lb = __float2bfloat16(lo);
        g_WTl[k * D_ + d] = *reinterpret_cast<unsigned short*>(&lb);
    }
}

// ================= GEMM1: assignment + softmax ===============================
#define AH1 0
#define AL1 18432
#define BH1 36864
#define BL1 46080
#define BIAS1 55296
#define SMEM1 55552

#define ASG_MMA()                                                              \
    do {                                                                       \
        _Pragma("unroll")                                                      \
        for (int ks = 0; ks < 4; ks++) {                                       \
            uint32_t ah[2][4], al[2][4], bh[2][4], bl[2][4];                   \
            _Pragma("unroll")                                                  \
            for (int mt = 0; mt < 2; mt++) {                                   \
                uint32_t ad = sb + AH1 + (wm * 32 + mt * 16 + (lane & 15)) * RB\
                              + (ks * 16 + (lane >> 4) * 8) * 2;               \
                ldm4(ah[mt], ad);                                              \
                ldm4(al[mt], ad + (AL1 - AH1));                                \
            }                                                                  \
            _Pragma("unroll")                                                  \
            for (int np = 0; np < 2; np++) {                                   \
                uint32_t bd = sb + BH1 +                                       \
                    (wn * 32 + np * 16 + (lane & 7) + ((lane >> 4) << 3)) * RB \
                    + (ks * 16 + ((lane >> 3) & 1) * 8) * 2;                   \
                ldm4(bh[np], bd);                                              \
                ldm4(bl[np], bd + (BL1 - BH1));                                \
            }                                                                  \
            _Pragma("unroll")                                                  \
            for (int mt = 0; mt < 2; mt++)                                     \
                _Pragma("unroll")                                              \
                for (int nt = 0; nt < 4; nt++) {                               \
                    const uint32_t* bph = &bh[nt >> 1][(nt & 1) * 2];          \
                    const uint32_t* bpl = &bl[nt >> 1][(nt & 1) * 2];          \
                    mma16816(acc[mt][nt], ah[mt], bph);                        \
                    mma16816(acc[mt][nt], ah[mt], bpl);                        \
                    mma16816(acc[mt][nt], al[mt], bph);                        \
                }                                                              \
        }                                                                      \
    } while (0)

__global__ void __launch_bounds__(256, 2)
asg_kernel(const float* __restrict__ x, const float* __restrict__ bc) {
    extern __shared__ char sm[];
    const int tid = threadIdx.x, lane = tid & 31, wid = tid >> 5;
    const int wm = wid & 3, wn = wid >> 2;
    const int row0 = blockIdx.x * 128, n = blockIdx.x >> 3;
    const int hw0 = row0 & (HW_ - 1);
    const uint32_t sb = smem_u32(sm);

    if (tid < 64) ((float*)(sm + BIAS1))[tid] = bc[tid];

    float acc[2][4][4];
#pragma unroll
    for (int a = 0; a < 2; a++)
#pragma unroll
        for (int b = 0; b < 4; b++)
#pragma unroll
            for (int c = 0; c < 4; c++) acc[a][b][c] = 0.f;

    float4 ra[8];
    uint4 rbh[2], rbl[2];
    const int arow = tid >> 1, aseg = (tid & 1) * 4;
    const int brow = tid >> 2, bseg = (tid & 3) * 16;

    // load chunk 0
#pragma unroll
    for (int j = 0; j < 8; j++)
        ra[j] = *(const float4*)(x + (size_t)(row0 + arow) * D_ + aseg + 8 * j);
    rbh[0] = *(const uint4*)(g_WTh + brow * D_ + bseg);
    rbh[1] = *(const uint4*)(g_WTh + brow * D_ + bseg + 8);
    rbl[0] = *(const uint4*)(g_WTl + brow * D_ + bseg);
    rbl[1] = *(const uint4*)(g_WTl + brow * D_ + bseg + 8);
    // store chunk 0
#pragma unroll
    for (int j = 0; j < 8; j++) {
        uint32_t h01, l01, h23, l23;
        split2(ra[j].x, ra[j].y, h01, l01);
        split2(ra[j].z, ra[j].w, h23, l23);
        uint32_t off = arow * RB + (aseg + 8 * j) * 2;
        *(uint2*)(sm + AH1 + off) = make_uint2(h01, h23);
        *(uint2*)(sm + AL1 + off) = make_uint2(l01, l23);
    }
    *(uint4*)(sm + BH1 + brow * RB + bseg * 2) = rbh[0];
    *(uint4*)(sm + BH1 + brow * RB + bseg * 2 + 16) = rbh[1];
    *(uint4*)(sm + BL1 + brow * RB + bseg * 2) = rbl[0];
    *(uint4*)(sm + BL1 + brow * RB + bseg * 2 + 16) = rbl[1];
    __syncthreads();

    for (int ch = 0; ch < 8; ch++) {
        if (ch < 7) {       // prefetch next chunk into regs (overlaps MMA)
            const float* xp = x + (size_t)(row0 + arow) * D_ + (ch + 1) * 64 + aseg;
#pragma unroll
            for (int j = 0; j < 8; j++) ra[j] = *(const float4*)(xp + 8 * j);
            const unsigned short* wh = g_WTh + brow * D_ + (ch + 1) * 64 + bseg;
            const unsigned short* wl = g_WTl + brow * D_ + (ch + 1) * 64 + bseg;
            rbh[0] = *(const uint4*)wh; rbh[1] = *(const uint4*)(wh + 8);
            rbl[0] = *(const uint4*)wl; rbl[1] = *(const uint4*)(wl + 8);
        }
        ASG_MMA();
        __syncthreads();
        if (ch < 7) {
#pragma unroll
            for (int j = 0; j < 8; j++) {
                uint32_t h01, l01, h23, l23;
                split2(ra[j].x, ra[j].y, h01, l01);
                split2(ra[j].z, ra[j].w, h23, l23);
                uint32_t off = arow * RB + (aseg + 8 * j) * 2;
                *(uint2*)(sm + AH1 + off) = make_uint2(h01, h23);
                *(uint2*)(sm + AL1 + off) = make_uint2(l01, l23);
            }
            *(uint4*)(sm + BH1 + brow * RB + bseg * 2) = rbh[0];
            *(uint4*)(sm + BH1 + brow * RB + bseg * 2 + 16) = rbh[1];
            *(uint4*)(sm + BL1 + brow * RB + bseg * 2) = rbl[0];
            *(uint4*)(sm + BL1 + brow * RB + bseg * 2 + 16) = rbl[1];
            __syncthreads();
        }
    }

    // scores -> SMEM s[128][66]
    float* s = (float*)sm;
#pragma unroll
    for (int mt = 0; mt < 2; mt++)
#pragma unroll
        for (int nt = 0; nt < 4; nt++) {
            int r = wm * 32 + mt * 16 + (lane >> 2);
            int col = wn * 32 + nt * 8 + 2 * (lane & 3);
            *(float2*)&s[r * 66 + col] = make_float2(acc[mt][nt][0], acc[mt][nt][1]);
            *(float2*)&s[(r + 8) * 66 + col] = make_float2(acc[mt][nt][2], acc[mt][nt][3]);
        }
    __syncthreads();

    // softmax on all 256 threads: 2 threads per row, 32 k each; pair combine
    // via shfl_xor(1) (partner is the adjacent lane)
    {
        const float* bias = (const float*)(sm + BIAS1);
        int row = tid >> 1, kh = (tid & 1) * 32;
        float f[32];
        float m = -1e30f;
#pragma unroll
        for (int k = 0; k < 32; k++) {
            f[k] = s[row * 66 + kh + k] + bias[kh + k];
            m = fmaxf(m, f[k]);
        }
        m = fmaxf(m, __shfl_xor_sync(0xffffffffu, m, 1));
        float ssum = 0.f;
#pragma unroll
        for (int k = 0; k < 32; k++) { f[k] = fexp(f[k] - m); ssum += f[k]; }
        ssum += __shfl_xor_sync(0xffffffffu, ssum, 1);
        float inv = 1.0f / ssum;
#pragma unroll
        for (int k = 0; k < 32; k++) s[row * 66 + kh + k] = f[k] * inv;
    }
    __syncthreads();

    // coalesced a^T write
    {
        size_t nb = (size_t)n * K_ * HW_;
#pragma unroll
        for (int kk = 0; kk < 8; kk++) {
            int k = wid * 8 + kk;
#pragma unroll
            for (int half = 0; half < 2; half++) {
                int hw = half * 64 + 2 * lane;
                float a0 = s[hw * 66 + k];
                float a1 = s[(hw + 1) * 66 + k];
                uint32_t hp, lp;
                split2(a0, a1, hp, lp);
                size_t e = nb + (size_t)k * HW_ + hw0 + hw;
                *(uint32_t*)(g_aTh + e) = hp;
                *(uint32_t*)(g_aTl + e) = lp;
            }
        }
    }
    if (tid < 64) {
        float acc_s = 0.f;
#pragma unroll 8
        for (int r = 0; r < 128; r++) acc_s += s[r * 66 + tid];
        atomicAdd(&g_asum[n * K_ + tid], acc_s);
    }
}

// ================= GEMM2: V^T = a^T (64xHW) * x (HWx128d) ====================
#define AH2 0
#define AL2 9216
#define BH2 18432
#define BL2 35840
#define AS2 53248
#define SMEM2 53504
#define VST 68       // v2 row stride in floats (272B, 16B-aligned)

__global__ void __launch_bounds__(256, 2)
vlad_kernel(const float* __restrict__ x, const float* __restrict__ Cc,
            float* __restrict__ out) {
    extern __shared__ char sm[];
    const int tid = threadIdx.x, lane = tid & 31, wid = tid >> 5;
    const int wm = wid & 1, wn = wid >> 1;
    const int n = blockIdx.y, m0 = blockIdx.x * 128;
    const uint32_t sb = smem_u32(sm);

    if (tid < 64) ((float*)(sm + AS2))[tid] = g_asum[n * K_ + tid];

    const float* xn = x + (size_t)n * HW_ * D_;
    const unsigned short* ath = g_aTh + (size_t)n * K_ * HW_;
    const unsigned short* atl = g_aTl + (size_t)n * K_ * HW_;

    float acc[2][4][4];
#pragma unroll
    for (int a = 0; a < 2; a++)
#pragma unroll
        for (int b = 0; b < 4; b++)
#pragma unroll
            for (int c = 0; c < 4; c++) acc[a][b][c] = 0.f;

    uint4 rah[2], ral[2];
    float4 rb[8];
    const int crow = tid >> 2, cseg = (tid & 3) * 16;
    const int xrow = tid >> 2, xseg = (tid & 3) * 4;

    // load chunk 0
    rah[0] = *(const uint4*)(ath + (size_t)crow * HW_ + cseg);
    rah[1] = *(const uint4*)(ath + (size_t)crow * HW_ + cseg + 8);
    ral[0] = *(const uint4*)(atl + (size_t)crow * HW_ + cseg);
    ral[1] = *(const uint4*)(atl + (size_t)crow * HW_ + cseg + 8);
#pragma unroll
    for (int j = 0; j < 8; j++)
        rb[j] = *(const float4*)(xn + (size_t)xrow * D_ + m0 + xseg + 16 * j);
    // store chunk 0
    *(uint4*)(sm + AH2 + crow * RB + cseg * 2) = rah[0];
    *(uint4*)(sm + AH2 + crow * RB + cseg * 2 + 16) = rah[1];
    *(uint4*)(sm + AL2 + crow * RB + cseg * 2) = ral[0];
    *(uint4*)(sm + AL2 + crow * RB + cseg * 2 + 16) = ral[1];
#pragma unroll
    for (int j = 0; j < 8; j++) {
        uint32_t h01, l01, h23, l23;
        split2(rb[j].x, rb[j].y, h01, l01);
        split2(rb[j].z, rb[j].w, h23, l23);
        uint32_t off = xrow * RB2 + (xseg + 16 * j) * 2;
        *(uint2*)(sm + BH2 + off) = make_uint2(h01, h23);
        *(uint2*)(sm + BL2 + off) = make_uint2(l01, l23);
    }
    __syncthreads();

    for (int ch = 0; ch < 16; ch++) {
        if (ch < 15) {   // prefetch next chunk into regs
            int hw1 = (ch + 1) * 64;
            const unsigned short* ah = ath + (size_t)crow * HW_ + hw1 + cseg;
            const unsigned short* al = atl + (size_t)crow * HW_ + hw1 + cseg;
            rah[0] = *(const uint4*)ah; rah[1] = *(const uint4*)(ah + 8);
            ral[0] = *(const uint4*)al; ral[1] = *(const uint4*)(al + 8);
            const float* xp = xn + (size_t)(hw1 + xrow) * D_ + m0 + xseg;
#pragma unroll
            for (int j = 0; j < 8; j++) rb[j] = *(const float4*)(xp + 16 * j);
        }
        // MMA on current tiles
#pragma unroll
        for (int ks = 0; ks < 4; ks++) {
            uint32_t ah[2][4], al[2][4], bh[2][4], bl[2][4];
#pragma unroll
            for (int mt = 0; mt < 2; mt++) {
                uint32_t ad = sb + AH2 + (wm * 32 + mt * 16 + (lane & 15)) * RB
                              + (ks * 16 + (lane >> 4) * 8) * 2;
                ldm4(ah[mt], ad);
                ldm4(al[mt], ad + (AL2 - AH2));
            }
#pragma unroll
            for (int np = 0; np < 2; np++) {
                uint32_t bd = sb + BH2 + (ks * 16 + (lane & 15)) * RB2
                              + (wn * 32 + np * 16 + (lane >> 4) * 8) * 2;
                ldm4t(bh[np], bd);
                ldm4t(bl[np], bd + (BL2 - BH2));
            }
#pragma unroll
            for (int mt = 0; mt < 2; mt++)
#pragma unroll
                for (int nt = 0; nt < 4; nt++) {
                    const uint32_t* bph = &bh[nt >> 1][(nt & 1) * 2];
                    const uint32_t* bpl = &bl[nt >> 1][(nt & 1) * 2];
                    mma16816(acc[mt][nt], ah[mt], bph);
                    mma16816(acc[mt][nt], ah[mt], bpl);
                    mma16816(acc[mt][nt], al[mt], bph);
                }
        }
        __syncthreads();
        if (ch < 15) {
            *(uint4*)(sm + AH2 + crow * RB + cseg * 2) = rah[0];
            *(uint4*)(sm + AH2 + crow * RB + cseg * 2 + 16) = rah[1];
            *(uint4*)(sm + AL2 + crow * RB + cseg * 2) = ral[0];
            *(uint4*)(sm + AL2 + crow * RB + cseg * 2 + 16) = ral[1];
#pragma unroll
            for (int j = 0; j < 8; j++) {
                uint32_t h01, l01, h23, l23;
                split2(rb[j].x, rb[j].y, h01, l01);
                split2(rb[j].z, rb[j].w, h23, l23);
                uint32_t off = xrow * RB2 + (xseg + 16 * j) * 2;
                *(uint2*)(sm + BH2 + off) = make_uint2(h01, h23);
                *(uint2*)(sm + BL2 + off) = make_uint2(l01, l23);
            }
            __syncthreads();
        }
    }

    // epilogue: acc (c,d) -> smem v2[d][VST] transposed
    float* v2 = (float*)sm;
#pragma unroll
    for (int mt = 0; mt < 2; mt++)
#pragma unroll
        for (int nt = 0; nt < 4; nt++) {
            int c = wm * 32 + mt * 16 + (lane >> 2);
            int d = wn * 32 + nt * 8 + 2 * (lane & 3);
            v2[d * VST + c] = acc[mt][nt][0];
            v2[(d + 1) * VST + c] = acc[mt][nt][1];
            v2[d * VST + c + 8] = acc[mt][nt][2];
            v2[(d + 1) * VST + c + 8] = acc[mt][nt][3];
        }
    __syncthreads();

    // output: +asum*C, coalesced store, o^2 back to v2 for colsq
    {
        const float* asums = (const float*)(sm + AS2);
        int d = tid >> 1, kh = (tid & 1) * 32;
        int dg = m0 + d;
        float* po = out + ((size_t)n * D_ + dg) * K_ + kh;
        const float* pc = Cc + (size_t)dg * K_ + kh;
#pragma unroll
        for (int j = 0; j < 8; j++) {
            float4 v = *(float4*)&v2[d * VST + kh + 4 * j];
            float4 cc = *(const float4*)(pc + 4 * j);
            float4 as = *(const float4*)(asums + kh + 4 * j);
            float4 o;
            o.x = fmaf(as.x, cc.x, v.x);
            o.y = fmaf(as.y, cc.y, v.y);
            o.z = fmaf(as.z, cc.z, v.z);
            o.w = fmaf(as.w, cc.w, v.w);
            *(float4*)(po + 4 * j) = o;
            float4 sq = make_float4(o.x * o.x, o.y * o.y, o.z * o.z, o.w * o.w);
            *(float4*)&v2[d * VST + kh + 4 * j] = sq;
        }
    }
    __syncthreads();
    if (tid < 64) {
        float s = 0.f;
#pragma unroll 8
        for (int d2 = 0; d2 < 128; d2++) s += v2[d2 * VST + tid];
        atomicAdd(&g_colsq[n * K_ + tid], s);
    }
}

// ---------------- apply: fused scale compute + streaming scale ---------------
__global__ void apply_kernel(float* __restrict__ out) {
    __shared__ float sc[64];
    __shared__ float part[2];
    const int n = blockIdx.y, tid = threadIdx.x;
    if (tid < 64) {
        float S = g_colsq[n * K_ + tid];
        float c = S / (S + EPSF);
#pragma unroll
        for (int o = 16; o >= 1; o >>= 1)
            c += __shfl_xor_sync(0xffffffffu, c, o);
        if ((tid & 31) == 0) part[tid >> 5] = c;
        sc[tid] = rsqrtf(S + EPSF);
    }
    __syncthreads();
    if (tid < 64) sc[tid] *= rsqrtf(part[0] + part[1] + EPSF);
    __syncthreads();
    float* po = out + (size_t)n * D_ * K_ + blockIdx.x * 2048;
#pragma unroll
    for (int i = 0; i < 2; i++) {
        int e = tid * 4 + i * 1024;
        float4 v = *(float4*)(po + e);
        int k = e & 63;
        v.x *= sc[k + 0]; v.y *= sc[k + 1];
        v.z *= sc[k + 2]; v.w *= sc[k + 3];
        *(float4*)(po + e) = v;
    }
}

// ---------------------------------------------------------------------------
extern "C" void kernel_launch(void* const* d_in, const int* in_sizes, int n_in,
                              void* d_out, int out_size) {
    const float* x = (const float*)d_in[0];   // [64,32,32,512]
    const float* W = (const float*)d_in[1];   // [512,64]
    const float* b = (const float*)d_in[2];   // [64]
    const float* C = (const float*)d_in[3];   // [512,64]
    float* out = (float*)d_out;               // [64, 32768]

    cudaFuncSetAttribute(asg_kernel, cudaFuncAttributeMaxDynamicSharedMemorySize, SMEM1);
    cudaFuncSetAttribute(vlad_kernel, cudaFuncAttributeMaxDynamicSharedMemorySize, SMEM2);

    prep_kernel<<<128, 256>>>(W);
    asg_kernel<<<512, 256, SMEM1>>>(x, b);
    vlad_kernel<<<dim3(4, 64), 256, SMEM2>>>(x, C, out);
    apply_kernel<<<dim3(16, 64), 256>>>(out);
}

// round 15
// speedup vs baseline: 1.2646x; 1.0079x over previous
#include <cuda_runtime.h>
#include <cuda_bf16.h>
#include <cstdint>

#define N_B 64
#define HW_ 1024
#define D_  512
#define K_  64
#define EPSF 1e-12f
#define RB   144     // A/B row bytes (72 bf16): ldmatrix conflict-free
#define RB2  272     // vlad B row bytes (136 bf16)

// ---------------- device scratch (allocation-free rule) ---------------------
__device__ unsigned short g_WTh[K_ * D_];                 // W^T hi bf16 [k][d]
__device__ unsigned short g_WTl[K_ * D_];                 // W^T lo bf16
__device__ unsigned short g_aTh[(size_t)N_B * K_ * HW_];  // a^T hi [n][k][hw]
__device__ unsigned short g_aTl[(size_t)N_B * K_ * HW_];  // a^T lo
__device__ float g_asum[N_B * K_];
__device__ float g_colsq[N_B * K_];

// ---------------- helpers ----------------------------------------------------
__device__ __forceinline__ uint32_t smem_u32(const void* p) {
    uint32_t a;
    asm("{ .reg .u64 t; cvta.to.shared.u64 t, %1; cvt.u32.u64 %0, t; }"
        : "=r"(a) : "l"(p));
    return a;
}
__device__ __forceinline__ void ldm4(uint32_t* r, uint32_t a) {
    asm volatile("ldmatrix.sync.aligned.m8n8.x4.shared.b16 {%0,%1,%2,%3}, [%4];"
                 : "=r"(r[0]), "=r"(r[1]), "=r"(r[2]), "=r"(r[3]) : "r"(a));
}
__device__ __forceinline__ void ldm4t(uint32_t* r, uint32_t a) {
    asm volatile("ldmatrix.sync.aligned.m8n8.x4.trans.shared.b16 {%0,%1,%2,%3}, [%4];"
                 : "=r"(r[0]), "=r"(r[1]), "=r"(r[2]), "=r"(r[3]) : "r"(a));
}
__device__ __forceinline__ void mma16816(float* d, const uint32_t* a,
                                         const uint32_t* b) {
    asm volatile(
        "mma.sync.aligned.m16n8k16.row.col.f32.bf16.bf16.f32 "
        "{%0,%1,%2,%3}, {%4,%5,%6,%7}, {%8,%9}, {%0,%1,%2,%3};"
        : "+f"(d[0]), "+f"(d[1]), "+f"(d[2]), "+f"(d[3])
        : "r"(a[0]), "r"(a[1]), "r"(a[2]), "r"(a[3]), "r"(b[0]), "r"(b[1]));
}
__device__ __forceinline__ void split2(float x0, float x1, uint32_t& hp, uint32_t& lp) {
    uint32_t u0 = __float_as_uint(x0), u1 = __float_as_uint(x1);
    hp = __byte_perm(u0, u1, 0x7632);
    float l0 = x0 - __uint_as_float(u0 & 0xFFFF0000u);
    float l1 = x1 - __uint_as_float(u1 & 0xFFFF0000u);
    asm("cvt.rn.bf16x2.f32 %0, %1, %2;" : "=r"(lp) : "f"(l1), "f"(l0));
}
__device__ __forceinline__ float fexp(float x) {
    x = fmaxf(x, -80.0f);
    float t = x * 1.4426950408889634f;
    float tb = t + 12582912.0f;
    float f = t - (tb - 12582912.0f);
    int ei = __float_as_int(tb) - 0x4B400000;
    float p = 1.5403530e-4f;
    p = fmaf(p, f, 1.3333558e-3f);
    p = fmaf(p, f, 9.6181291e-3f);
    p = fmaf(p, f, 5.5504109e-2f);
    p = fmaf(p, f, 2.4022651e-1f);
    p = fmaf(p, f, 6.9314718e-1f);
    p = fmaf(p, f, 1.0f);
    return p * __int_as_float((ei + 127) << 23);
}

// ---------------- prep: W split + accumulator zeroing ------------------------
__global__ void prep_kernel(const float* __restrict__ W) {
    int t = blockIdx.x * blockDim.x + threadIdx.x;
    if (t < N_B * K_) { g_asum[t] = 0.f; g_colsq[t] = 0.f; }
    if (t < D_ * K_) {
        int d = t >> 6, k = t & 63;
        float w = W[t];
        uint32_t u = __float_as_uint(w);
        g_WTh[k * D_ + d] = (unsigned short)(u >> 16);
        float lo = w - __uint_as_float(u & 0xFFFF0000u);
        __nv_bfloat16 lb = __float2bfloat16(lo);
        g_WTl[k * D_ + d] = *reinterpret_cast<unsigned short*>(&lb);
    }
}

// ================= GEMM1: assignment + softmax ===============================
#define AH1 0
#define AL1 18432
#define BH1 36864
#define BL1 46080
#define BIAS1 55296
#define SMEM1 55552

#define ASG_MMA()                                                              \
    do {                                                                       \
        _Pragma("unroll")                                                      \
        for (int ks = 0; ks < 4; ks++) {                                       \
            uint32_t ah[2][4], al[2][4], bh[2][4], bl[2][4];                   \
            _Pragma("unroll")                                                  \
            for (int mt = 0; mt < 2; mt++) {                                   \
                uint32_t ad = sb + AH1 + (wm * 32 + mt * 16 + (lane & 15)) * RB\
                              + (ks * 16 + (lane >> 4) * 8) * 2;               \
                ldm4(ah[mt], ad);                                              \
                ldm4(al[mt], ad + (AL1 - AH1));                                \
            }                                                                  \
            _Pragma("unroll")                                                  \
            for (int np = 0; np < 2; np++) {                                   \
                uint32_t bd = sb + BH1 +                                       \
                    (wn * 32 + np * 16 + (lane & 7) + ((lane >> 4) << 3)) * RB \
                    + (ks * 16 + ((lane >> 3) & 1) * 8) * 2;                   \
                ldm4(bh[np], bd);                                              \
                ldm4(bl[np], bd + (BL1 - BH1));                                \
            }                                                                  \
            _Pragma("unroll")                                                  \
            for (int mt = 0; mt < 2; mt++)                                     \
                _Pragma("unroll")                                              \
                for (int nt = 0; nt < 4; nt++) {                               \
                    const uint32_t* bph = &bh[nt >> 1][(nt & 1) * 2];          \
                    const uint32_t* bpl = &bl[nt >> 1][(nt & 1) * 2];          \
                    mma16816(acc[mt][nt], ah[mt], bph);                        \
                    mma16816(acc[mt][nt], ah[mt], bpl);                        \
                    mma16816(acc[mt][nt], al[mt], bph);                        \
                }                                                              \
        }                                                                      \
    } while (0)

__global__ void __launch_bounds__(256, 2)
asg_kernel(const float* __restrict__ x, const float* __restrict__ bc) {
    extern __shared__ char sm[];
    const int tid = threadIdx.x, lane = tid & 31, wid = tid >> 5;
    const int wm = wid & 3, wn = wid >> 2;
    const int row0 = blockIdx.x * 128, n = blockIdx.x >> 3;
    const int hw0 = row0 & (HW_ - 1);
    const uint32_t sb = smem_u32(sm);

    if (tid < 64) ((float*)(sm + BIAS1))[tid] = bc[tid];

    float acc[2][4][4];
#pragma unroll
    for (int a = 0; a < 2; a++)
#pragma unroll
        for (int b = 0; b < 4; b++)
#pragma unroll
            for (int c = 0; c < 4; c++) acc[a][b][c] = 0.f;

    float4 ra[8];
    uint4 rbh[2], rbl[2];
    const int arow = tid >> 1, aseg = (tid & 1) * 4;
    const int brow = tid >> 2, bseg = (tid & 3) * 16;

    // load chunk 0
#pragma unroll
    for (int j = 0; j < 8; j++)
        ra[j] = *(const float4*)(x + (size_t)(row0 + arow) * D_ + aseg + 8 * j);
    rbh[0] = *(const uint4*)(g_WTh + brow * D_ + bseg);
    rbh[1] = *(const uint4*)(g_WTh + brow * D_ + bseg + 8);
    rbl[0] = *(const uint4*)(g_WTl + brow * D_ + bseg);
    rbl[1] = *(const uint4*)(g_WTl + brow * D_ + bseg + 8);
    // store chunk 0
#pragma unroll
    for (int j = 0; j < 8; j++) {
        uint32_t h01, l01, h23, l23;
        split2(ra[j].x, ra[j].y, h01, l01);
        split2(ra[j].z, ra[j].w, h23, l23);
        uint32_t off = arow * RB + (aseg + 8 * j) * 2;
        *(uint2*)(sm + AH1 + off) = make_uint2(h01, h23);
        *(uint2*)(sm + AL1 + off) = make_uint2(l01, l23);
    }
    *(uint4*)(sm + BH1 + brow * RB + bseg * 2) = rbh[0];
    *(uint4*)(sm + BH1 + brow * RB + bseg * 2 + 16) = rbh[1];
    *(uint4*)(sm + BL1 + brow * RB + bseg * 2) = rbl[0];
    *(uint4*)(sm + BL1 + brow * RB + bseg * 2 + 16) = rbl[1];
    __syncthreads();

    for (int ch = 0; ch < 8; ch++) {
        if (ch < 7) {       // prefetch next chunk into regs (overlaps MMA)
            const float* xp = x + (size_t)(row0 + arow) * D_ + (ch + 1) * 64 + aseg;
#pragma unroll
            for (int j = 0; j < 8; j++) ra[j] = *(const float4*)(xp + 8 * j);
            const unsigned short* wh = g_WTh + brow * D_ + (ch + 1) * 64 + bseg;
            const unsigned short* wl = g_WTl + brow * D_ + (ch + 1) * 64 + bseg;
            rbh[0] = *(const uint4*)wh; rbh[1] = *(const uint4*)(wh + 8);
            rbl[0] = *(const uint4*)wl; rbl[1] = *(const uint4*)(wl + 8);
        }
        ASG_MMA();
        __syncthreads();
        if (ch < 7) {
#pragma unroll
            for (int j = 0; j < 8; j++) {
                uint32_t h01, l01, h23, l23;
                split2(ra[j].x, ra[j].y, h01, l01);
                split2(ra[j].z, ra[j].w, h23, l23);
                uint32_t off = arow * RB + (aseg + 8 * j) * 2;
                *(uint2*)(sm + AH1 + off) = make_uint2(h01, h23);
                *(uint2*)(sm + AL1 + off) = make_uint2(l01, l23);
            }
            *(uint4*)(sm + BH1 + brow * RB + bseg * 2) = rbh[0];
            *(uint4*)(sm + BH1 + brow * RB + bseg * 2 + 16) = rbh[1];
            *(uint4*)(sm + BL1 + brow * RB + bseg * 2) = rbl[0];
            *(uint4*)(sm + BL1 + brow * RB + bseg * 2 + 16) = rbl[1];
            __syncthreads();
        }
    }

    // scores -> SMEM s[128][66]
    float* s = (float*)sm;
#pragma unroll
    for (int mt = 0; mt < 2; mt++)
#pragma unroll
        for (int nt = 0; nt < 4; nt++) {
            int r = wm * 32 + mt * 16 + (lane >> 2);
            int col = wn * 32 + nt * 8 + 2 * (lane & 3);
            *(float2*)&s[r * 66 + col] = make_float2(acc[mt][nt][0], acc[mt][nt][1]);
            *(float2*)&s[(r + 8) * 66 + col] = make_float2(acc[mt][nt][2], acc[mt][nt][3]);
        }
    __syncthreads();

    // softmax on all 256 threads: 2 threads per row, 32 k each; pair combine
    {
        const float* bias = (const float*)(sm + BIAS1);
        int row = tid >> 1, kh = (tid & 1) * 32;
        float f[32];
        float m = -1e30f;
#pragma unroll
        for (int k = 0; k < 32; k++) {
            f[k] = s[row * 66 + kh + k] + bias[kh + k];
            m = fmaxf(m, f[k]);
        }
        m = fmaxf(m, __shfl_xor_sync(0xffffffffu, m, 1));
        float ssum = 0.f;
#pragma unroll
        for (int k = 0; k < 32; k++) { f[k] = fexp(f[k] - m); ssum += f[k]; }
        ssum += __shfl_xor_sync(0xffffffffu, ssum, 1);
        float inv = 1.0f / ssum;
#pragma unroll
        for (int k = 0; k < 32; k++) s[row * 66 + kh + k] = f[k] * inv;
    }
    __syncthreads();

    // coalesced a^T write
    {
        size_t nb = (size_t)n * K_ * HW_;
#pragma unroll
        for (int kk = 0; kk < 8; kk++) {
            int k = wid * 8 + kk;
#pragma unroll
            for (int half = 0; half < 2; half++) {
                int hw = half * 64 + 2 * lane;
                float a0 = s[hw * 66 + k];
                float a1 = s[(hw + 1) * 66 + k];
                uint32_t hp, lp;
                split2(a0, a1, hp, lp);
                size_t e = nb + (size_t)k * HW_ + hw0 + hw;
                *(uint32_t*)(g_aTh + e) = hp;
                *(uint32_t*)(g_aTl + e) = lp;
            }
        }
    }
    // a_sum: 256 threads, 32 rows each (4 partial atomics per k)
    {
        int k = tid & 63, q = tid >> 6;
        float acc_s = 0.f;
#pragma unroll 8
        for (int r = q * 32; r < q * 32 + 32; r++) acc_s += s[r * 66 + k];
        atomicAdd(&g_asum[n * K_ + k], acc_s);
    }
}

// ================= GEMM2: V^T = a^T (64xHW) * x (HWx128d) ====================
#define AH2 0
#define AL2 9216
#define BH2 18432
#define BL2 35840
#define AS2 53248
#define SMEM2 53504
#define VST 68       // v2 row stride in floats (272B, 16B-aligned)

__global__ void __launch_bounds__(256, 2)
vlad_kernel(const float* __restrict__ x, const float* __restrict__ Cc,
            float* __restrict__ out) {
    extern __shared__ char sm[];
    const int tid = threadIdx.x, lane = tid & 31, wid = tid >> 5;
    const int wm = wid & 1, wn = wid >> 1;
    const int n = blockIdx.y, m0 = blockIdx.x * 128;
    const uint32_t sb = smem_u32(sm);

    if (tid < 64) ((float*)(sm + AS2))[tid] = g_asum[n * K_ + tid];

    const float* xn = x + (size_t)n * HW_ * D_;
    const unsigned short* ath = g_aTh + (size_t)n * K_ * HW_;
    const unsigned short* atl = g_aTl + (size_t)n * K_ * HW_;

    float acc[2][4][4];
#pragma unroll
    for (int a = 0; a < 2; a++)
#pragma unroll
        for (int b = 0; b < 4; b++)
#pragma unroll
            for (int c = 0; c < 4; c++) acc[a][b][c] = 0.f;

    uint4 rah[2], ral[2];
    float4 rb[8];
    const int crow = tid >> 2, cseg = (tid & 3) * 16;
    const int xrow = tid >> 2, xseg = (tid & 3) * 4;

    // load chunk 0
    rah[0] = *(const uint4*)(ath + (size_t)crow * HW_ + cseg);
    rah[1] = *(const uint4*)(ath + (size_t)crow * HW_ + cseg + 8);
    ral[0] = *(const uint4*)(atl + (size_t)crow * HW_ + cseg);
    ral[1] = *(const uint4*)(atl + (size_t)crow * HW_ + cseg + 8);
#pragma unroll
    for (int j = 0; j < 8; j++)
        rb[j] = *(const float4*)(xn + (size_t)xrow * D_ + m0 + xseg + 16 * j);
    // store chunk 0
    *(uint4*)(sm + AH2 + crow * RB + cseg * 2) = rah[0];
    *(uint4*)(sm + AH2 + crow * RB + cseg * 2 + 16) = rah[1];
    *(uint4*)(sm + AL2 + crow * RB + cseg * 2) = ral[0];
    *(uint4*)(sm + AL2 + crow * RB + cseg * 2 + 16) = ral[1];
#pragma unroll
    for (int j = 0; j < 8; j++) {
        uint32_t h01, l01, h23, l23;
        split2(rb[j].x, rb[j].y, h01, l01);
        split2(rb[j].z, rb[j].w, h23, l23);
        uint32_t off = xrow * RB2 + (xseg + 16 * j) * 2;
        *(uint2*)(sm + BH2 + off) = make_uint2(h01, h23);
        *(uint2*)(sm + BL2 + off) = make_uint2(l01, l23);
    }
    __syncthreads();

    for (int ch = 0; ch < 16; ch++) {
        if (ch < 15) {   // prefetch next chunk into regs
            int hw1 = (ch + 1) * 64;
            const unsigned short* ah = ath + (size_t)crow * HW_ + hw1 + cseg;
            const unsigned short* al = atl + (size_t)crow * HW_ + hw1 + cseg;
            rah[0] = *(const uint4*)ah; rah[1] = *(const uint4*)(ah + 8);
            ral[0] = *(const uint4*)al; ral[1] = *(const uint4*)(al + 8);
            const float* xp = xn + (size_t)(hw1 + xrow) * D_ + m0 + xseg;
#pragma unroll
            for (int j = 0; j < 8; j++) rb[j] = *(const float4*)(xp + 16 * j);
        }
        // MMA on current tiles
#pragma unroll
        for (int ks = 0; ks < 4; ks++) {
            uint32_t ah[2][4], al[2][4], bh[2][4], bl[2][4];
#pragma unroll
            for (int mt = 0; mt < 2; mt++) {
                uint32_t ad = sb + AH2 + (wm * 32 + mt * 16 + (lane & 15)) * RB
                              + (ks * 16 + (lane >> 4) * 8) * 2;
                ldm4(ah[mt], ad);
                ldm4(al[mt], ad + (AL2 - AH2));
            }
#pragma unroll
            for (int np = 0; np < 2; np++) {
                uint32_t bd = sb + BH2 + (ks * 16 + (lane & 15)) * RB2
                              + (wn * 32 + np * 16 + (lane >> 4) * 8) * 2;
                ldm4t(bh[np], bd);
                ldm4t(bl[np], bd + (BL2 - BH2));
            }
#pragma unroll
            for (int mt = 0; mt < 2; mt++)
#pragma unroll
                for (int nt = 0; nt < 4; nt++) {
                    const uint32_t* bph = &bh[nt >> 1][(nt & 1) * 2];
                    const uint32_t* bpl = &bl[nt >> 1][(nt & 1) * 2];
                    mma16816(acc[mt][nt], ah[mt], bph);
                    mma16816(acc[mt][nt], ah[mt], bpl);
                    mma16816(acc[mt][nt], al[mt], bph);
                }
        }
        __syncthreads();
        if (ch < 15) {
            *(uint4*)(sm + AH2 + crow * RB + cseg * 2) = rah[0];
            *(uint4*)(sm + AH2 + crow * RB + cseg * 2 + 16) = rah[1];
            *(uint4*)(sm + AL2 + crow * RB + cseg * 2) = ral[0];
            *(uint4*)(sm + AL2 + crow * RB + cseg * 2 + 16) = ral[1];
#pragma unroll
            for (int j = 0; j < 8; j++) {
                uint32_t h01, l01, h23, l23;
                split2(rb[j].x, rb[j].y, h01, l01);
                split2(rb[j].z, rb[j].w, h23, l23);
                uint32_t off = xrow * RB2 + (xseg + 16 * j) * 2;
                *(uint2*)(sm + BH2 + off) = make_uint2(h01, h23);
                *(uint2*)(sm + BL2 + off) = make_uint2(l01, l23);
            }
            __syncthreads();
        }
    }

    // epilogue: acc (c,d) -> smem v2[d][VST] transposed
    float* v2 = (float*)sm;
#pragma unroll
    for (int mt = 0; mt < 2; mt++)
#pragma unroll
        for (int nt = 0; nt < 4; nt++) {
            int c = wm * 32 + mt * 16 + (lane >> 2);
            int d = wn * 32 + nt * 8 + 2 * (lane & 3);
            v2[d * VST + c] = acc[mt][nt][0];
            v2[(d + 1) * VST + c] = acc[mt][nt][1];
            v2[d * VST + c + 8] = acc[mt][nt][2];
            v2[(d + 1) * VST + c + 8] = acc[mt][nt][3];
        }
    __syncthreads();

    // output: +asum*C, coalesced store, o^2 back to v2 for colsq
    {
        const float* asums = (const float*)(sm + AS2);
        int d = tid >> 1, kh = (tid & 1) * 32;
        int dg = m0 + d;
        float* po = out + ((size_t)n * D_ + dg) * K_ + kh;
        const float* pc = Cc + (size_t)dg * K_ + kh;
#pragma unroll
        for (int j = 0; j < 8; j++) {
            float4 v = *(float4*)&v2[d * VST + kh + 4 * j];
            float4 cc = *(const float4*)(pc + 4 * j);
            float4 as = *(const float4*)(asums + kh + 4 * j);
            float4 o;
            o.x = fmaf(as.x, cc.x, v.x);
            o.y = fmaf(as.y, cc.y, v.y);
            o.z = fmaf(as.z, cc.z, v.z);
            o.w = fmaf(as.w, cc.w, v.w);
            *(float4*)(po + 4 * j) = o;
            float4 sq = make_float4(o.x * o.x, o.y * o.y, o.z * o.z, o.w * o.w);
            *(float4*)&v2[d * VST + kh + 4 * j] = sq;
        }
    }
    __syncthreads();
    // colsq: 256 threads, 32 rows each (4 partial atomics per k)
    {
        int k = tid & 63, q = tid >> 6;
        float s = 0.f;
#pragma unroll 8
        for (int d2 = q * 32; d2 < q * 32 + 32; d2++) s += v2[d2 * VST + k];
        atomicAdd(&g_colsq[n * K_ + k], s);
    }
}

// ---------------- apply: fused scale compute + streaming scale ---------------
__global__ void apply_kernel(float* __restrict__ out) {
    __shared__ float sc[64];
    __shared__ float part[2];
    const int n = blockIdx.y, tid = threadIdx.x;
    if (tid < 64) {
        float S = g_colsq[n * K_ + tid];
        float c = S / (S + EPSF);
#pragma unroll
        for (int o = 16; o >= 1; o >>= 1)
            c += __shfl_xor_sync(0xffffffffu, c, o);
        if ((tid & 31) == 0) part[tid >> 5] = c;
        sc[tid] = rsqrtf(S + EPSF);
    }
    __syncthreads();
    if (tid < 64) sc[tid] *= rsqrtf(part[0] + part[1] + EPSF);
    __syncthreads();
    float* po = out + (size_t)n * D_ * K_ + blockIdx.x * 4096;
#pragma unroll
    for (int i = 0; i < 4; i++) {
        int e = tid * 4 + i * 1024;
        float4 v = *(float4*)(po + e);
        int k = e & 63;
        v.x *= sc[k + 0]; v.y *= sc[k + 1];
        v.z *= sc[k + 2]; v.w *= sc[k + 3];
        *(float4*)(po + e) = v;
    }
}

// ---------------------------------------------------------------------------
extern "C" void kernel_launch(void* const* d_in, const int* in_sizes, int n_in,
                              void* d_out, int out_size) {
    const float* x = (const float*)d_in[0];   // [64,32,32,512]
    const float* W = (const float*)d_in[1];   // [512,64]
    const float* b = (const float*)d_in[2];   // [64]
    const float* C = (const float*)d_in[3];   // [512,64]
    float* out = (float*)d_out;               // [64, 32768]

    cudaFuncSetAttribute(asg_kernel, cudaFuncAttributeMaxDynamicSharedMemorySize, SMEM1);
    cudaFuncSetAttribute(vlad_kernel, cudaFuncAttributeMaxDynamicSharedMemorySize, SMEM2);

    prep_kernel<<<128, 256>>>(W);
    asg_kernel<<<512, 256, SMEM1>>>(x, b);
    vlad_kernel<<<dim3(4, 64), 256, SMEM2>>>(x, C, out);
    apply_kernel<<<dim3(8, 64), 256>>>(out);
}